// round 6
// baseline (speedup 1.0000x reference)
#include <cuda_runtime.h>
#include <cuda_bf16.h>
#include <cstdint>

// ---------------------------------------------------------------------------
// WindowedCrossAttention — R6
//   GEMMs: 2-pass hybrid  C = Ah*Bh (bf16 HMMA) + [Al'*B8 + A8*Bl']/4096 (fp8 HMMA)
//   Attention: online softmax, register Q, LDS.128, smem bias
// ---------------------------------------------------------------------------

__device__ float g_Q [4096ull * 64ull * 256ull];
__device__ float g_KV[4096ull * 64ull * 512ull];
__device__ float g_O [4096ull * 64ull * 256ull];
__device__ float g_bias[8 * 64 * 64];                 // [h][m][n]
__device__ __nv_bfloat16 g_Wthi[512 * 256];           // bf16 hi, [n][k]
__device__ unsigned char g_W8h[512 * 256];            // e4m3(W*16)
__device__ unsigned char g_W8l[512 * 256];            // e4m3((W-hi)*4096)

// ---- helpers ----------------------------------------------------------------
__device__ __forceinline__ uint32_t smem_u32(const void* p) {
    uint32_t a;
    asm("{ .reg .u64 t; cvta.to.shared.u64 t, %1; cvt.u32.u64 %0, t; }" : "=r"(a) : "l"(p));
    return a;
}
__device__ __forceinline__ unsigned long long pk2(float x) {
    unsigned long long r;
    asm("mov.b64 %0, {%1, %1};" : "=l"(r) : "r"(__float_as_uint(x)));
    return r;
}
__device__ __forceinline__ void fma2(unsigned long long& d, unsigned long long a,
                                     unsigned long long b) {
    asm("fma.rn.f32x2 %0, %1, %2, %0;" : "+l"(d) : "l"(a), "l"(b));
}
__device__ __forceinline__ void mul2(unsigned long long& d, unsigned long long f) {
    asm("mul.rn.f32x2 %0, %0, %1;" : "+l"(d) : "l"(f));
}
__device__ __forceinline__ void unpk(unsigned long long v, float& lo, float& hi) {
    unsigned int l, h;
    asm("mov.b64 {%0, %1}, %2;" : "=r"(l), "=r"(h) : "l"(v));
    lo = __uint_as_float(l);
    hi = __uint_as_float(h);
}
__device__ __forceinline__ void mma16816(float* c, const uint32_t* a, const uint32_t* b) {
    asm volatile(
        "mma.sync.aligned.m16n8k16.row.col.f32.bf16.bf16.f32 "
        "{%0,%1,%2,%3}, {%4,%5,%6,%7}, {%8,%9}, {%0,%1,%2,%3};"
        : "+f"(c[0]), "+f"(c[1]), "+f"(c[2]), "+f"(c[3])
        : "r"(a[0]), "r"(a[1]), "r"(a[2]), "r"(a[3]), "r"(b[0]), "r"(b[1]));
}
__device__ __forceinline__ void mma16832f8(float* c, const uint32_t* a, const uint32_t* b) {
    asm volatile(
        "mma.sync.aligned.m16n8k32.row.col.f32.e4m3.e4m3.f32 "
        "{%0,%1,%2,%3}, {%4,%5,%6,%7}, {%8,%9}, {%0,%1,%2,%3};"
        : "+f"(c[0]), "+f"(c[1]), "+f"(c[2]), "+f"(c[3])
        : "r"(a[0]), "r"(a[1]), "r"(a[2]), "r"(a[3]), "r"(b[0]), "r"(b[1]));
}
// pack 4 floats -> 4 e4m3 bytes (byte i = e4m3(f_i))
__device__ __forceinline__ uint32_t pk_e4m3_4(float a0, float a1, float a2, float a3) {
    uint16_t lo, hi;
    asm("cvt.rn.satfinite.e4m3x2.f32 %0, %1, %2;" : "=h"(lo) : "f"(a1), "f"(a0));
    asm("cvt.rn.satfinite.e4m3x2.f32 %0, %1, %2;" : "=h"(hi) : "f"(a3), "f"(a2));
    return (uint32_t)lo | ((uint32_t)hi << 16);
}
__device__ __forceinline__ unsigned char e4m3_1(float x) {
    uint16_t r;
    asm("cvt.rn.satfinite.e4m3x2.f32 %0, %1, %2;" : "=h"(r) : "f"(0.f), "f"(x));
    return (unsigned char)(r & 0xFF);
}
#define CP_ASYNC16(dst, src) \
    asm volatile("cp.async.cg.shared.global [%0], [%1], 16;" :: "r"(dst), "l"(src))
#define CP_COMMIT() asm volatile("cp.async.commit_group;")
#define CP_WAIT0()  asm volatile("cp.async.wait_group 0;")

// ---- relative-position bias (transposed [h][m][n]) ---------------------------
__global__ void bias_kernel(const float* __restrict__ bt) {
    int idx = blockIdx.x * 256 + threadIdx.x;
    if (idx >= 8 * 64 * 64) return;
    int h  = idx >> 12;
    int nm = idx & 4095;
    int m = nm >> 6, n = nm & 63;
    int dy = (n >> 3) - (m >> 3);
    int dx = (n & 7) - (m & 7);
    int r  = (dy + 7) * 15 + (dx + 7);
    g_bias[idx] = bt[r * 8 + h];
}

// ---- W -> bf16 hi + fp8 (W*16) + fp8 residual*4096, [n][k] -------------------
__global__ void convw_kernel(const float* __restrict__ W, int Ncols) {
    int idx = blockIdx.x * 256 + threadIdx.x;
    if (idx >= Ncols * 256) return;
    int n = idx >> 8;
    int k = idx & 255;
    float v = W[k * Ncols + n];
    __nv_bfloat16 h = __float2bfloat16(v);
    g_Wthi[idx] = h;
    g_W8h[idx] = e4m3_1(v * 16.f);
    g_W8l[idx] = e4m3_1((v - __bfloat162float(h)) * 4096.f);
}

// ---- hybrid GEMM:  C[M,N] = scale*(A[M,256] @ W + bias) ----------------------
// 512 threads, block 128x128, warp 32x32 (4x4), KC=32, ping-pong.
// Buffer layout (base = 1024 + buf*45056):
//   Ah  @0      128 x 80B  (bf16, pad 40)
//   Al8 @10240  128 x 48B  (e4m3 of (A-Ah)*256)
//   A8  @16384  128 x 48B  (e4m3 of A)
//   Bh  @22528  128 x 80B  (bf16)
//   B8h @32768  128 x 48B  (e4m3 of W*16)
//   B8l @38912  128 x 48B  (e4m3 of (W-Bh)*4096)
#define GSM_TOTAL (1024 + 2 * 45056)
#define AS 40

template <int N, int DSTSEL, int SRCSEL>
__global__ __launch_bounds__(512, 1)
void gemm_tc(const float* __restrict__ Ap, const float* __restrict__ bias,
             float* __restrict__ Cp, float scale) {
    extern __shared__ __align__(1024) char smem[];
    const uint32_t sb = smem_u32(smem);

    const float* A = (SRCSEL == 0) ? Ap : g_O;
    float* C = (DSTSEL == 0) ? g_Q : ((DSTSEL == 1) ? g_KV : Cp);

    const int tid  = threadIdx.x;
    const int wid  = tid >> 5, lane = tid & 31;
    const int g    = lane >> 2, tig = lane & 3;
    const int wm   = wid & 3, wn = wid >> 2;
    const int n0   = blockIdx.x * 128;
    const long long m0 = (long long)blockIdx.y * 128;

    float* sBias = (float*)smem;
    if (tid < 128) sBias[tid] = bias[n0 + tid];

    float acc[2][4][4];      // bf16 main
    float accq[2][4][4];     // fp8 corrections (scale 4096)
#pragma unroll
    for (int i = 0; i < 2; ++i)
#pragma unroll
        for (int j = 0; j < 4; ++j)
#pragma unroll
            for (int q = 0; q < 4; ++q) { acc[i][j][q] = 0.f; accq[i][j][q] = 0.f; }

    // ---- loaders ----
    auto loadA_regs = [&](int kc, float4* r) {
#pragma unroll
        for (int i = 0; i < 2; ++i) {
            int idx = tid + i * 512;
            int row = idx >> 3;
            int q = idx & 7;
            r[i] = *reinterpret_cast<const float4*>(
                A + (m0 + row) * 256 + kc * 32 + q * 4);
        }
    };
    auto stsA = [&](int buf, const float4* r) {
        char* base = smem + 1024 + buf * 45056;
#pragma unroll
        for (int i = 0; i < 2; ++i) {
            int idx = tid + i * 512;
            int row = idx >> 3;
            int q = idx & 7;
            float4 v = r[i];
            __nv_bfloat16 h0 = __float2bfloat16(v.x), h1 = __float2bfloat16(v.y);
            __nv_bfloat16 h2 = __float2bfloat16(v.z), h3 = __float2bfloat16(v.w);
            __nv_bfloat162 hA(h0, h1), hB(h2, h3);
            *reinterpret_cast<uint2*>(base + row * 80 + q * 8) =
                make_uint2(*reinterpret_cast<uint32_t*>(&hA),
                           *reinterpret_cast<uint32_t*>(&hB));
            // fp8 residual (A - Ah)*256
            float r0 = (v.x - __bfloat162float(h0)) * 256.f;
            float r1 = (v.y - __bfloat162float(h1)) * 256.f;
            float r2 = (v.z - __bfloat162float(h2)) * 256.f;
            float r3 = (v.w - __bfloat162float(h3)) * 256.f;
            *reinterpret_cast<uint32_t*>(base + 10240 + row * 48 + q * 4) =
                pk_e4m3_4(r0, r1, r2, r3);
            // fp8 of A itself
            *reinterpret_cast<uint32_t*>(base + 16384 + row * 48 + q * 4) =
                pk_e4m3_4(v.x, v.y, v.z, v.w);
        }
    };
    auto cpB = [&](int kc, int buf) {
        uint32_t base = sb + 1024 + buf * 45056;
        {   // Bh bf16: 128 rows x 4 segs of 16B
            int row = tid >> 2, seg = tid & 3;
            const __nv_bfloat16* src =
                g_Wthi + (long long)(n0 + row) * 256 + kc * 32 + seg * 8;
            CP_ASYNC16(base + 22528 + row * 80 + seg * 16, src);
        }
        {   // B8h / B8l: 128 rows x 2 halves of 16B each
            int row = tid >> 2, sub = tid & 3;
            int arr = sub >> 1, half = sub & 1;
            const unsigned char* src =
                (arr ? g_W8l : g_W8h) + (long long)(n0 + row) * 256 + kc * 32 + half * 16;
            CP_ASYNC16(base + (arr ? 38912 : 32768) + row * 48 + half * 16, src);
        }
    };
    auto mma_buf = [&](int buf) {
        char* base = smem + 1024 + buf * 45056;
        const __nv_bfloat16* Ahp = (const __nv_bfloat16*)(base);
        const __nv_bfloat16* Bhp = (const __nv_bfloat16*)(base + 22528);
        // ---- bf16 main term ----
#pragma unroll
        for (int ks = 0; ks < 2; ++ks) {
            const int k0 = ks * 16;
            uint32_t ah[2][4], bh[4][2];
#pragma unroll
            for (int mf = 0; mf < 2; ++mf) {
                const __nv_bfloat16* p = Ahp + (wm * 32 + mf * 16 + g) * AS + k0 + tig * 2;
                ah[mf][0] = *(const uint32_t*)p;
                ah[mf][1] = *(const uint32_t*)(p + 8 * AS);
                ah[mf][2] = *(const uint32_t*)(p + 8);
                ah[mf][3] = *(const uint32_t*)(p + 8 * AS + 8);
            }
#pragma unroll
            for (int nf = 0; nf < 4; ++nf) {
                const __nv_bfloat16* p = Bhp + (wn * 32 + nf * 8 + g) * AS + k0 + tig * 2;
                bh[nf][0] = *(const uint32_t*)p;
                bh[nf][1] = *(const uint32_t*)(p + 8);
            }
#pragma unroll
            for (int mf = 0; mf < 2; ++mf)
#pragma unroll
                for (int nf = 0; nf < 4; ++nf) mma16816(acc[mf][nf], ah[mf], bh[nf]);
        }
        // ---- fp8 corrections: Al'*B8h  and  A8*B8l (k=32 in one step) ----
#pragma unroll
        for (int t = 0; t < 2; ++t) {
            const char* Aq = base + (t == 0 ? 10240 : 16384);   // Al8 : A8
            const char* Bq = base + (t == 0 ? 32768 : 38912);   // B8h : B8l
            uint32_t af[2][4], bf[4][2];
#pragma unroll
            for (int mf = 0; mf < 2; ++mf) {
                const char* p = Aq + (wm * 32 + mf * 16 + g) * 48 + tig * 4;
                af[mf][0] = *(const uint32_t*)p;
                af[mf][1] = *(const uint32_t*)(p + 8 * 48);
                af[mf][2] = *(const uint32_t*)(p + 16);
                af[mf][3] = *(const uint32_t*)(p + 8 * 48 + 16);
            }
#pragma unroll
            for (int nf = 0; nf < 4; ++nf) {
                const char* p = Bq + (wn * 32 + nf * 8 + g) * 48 + tig * 4;
                bf[nf][0] = *(const uint32_t*)p;
                bf[nf][1] = *(const uint32_t*)(p + 16);
            }
#pragma unroll
            for (int mf = 0; mf < 2; ++mf)
#pragma unroll
                for (int nf = 0; nf < 4; ++nf) mma16832f8(accq[mf][nf], af[mf], bf[nf]);
        }
    };

    // ---- prologue ----
    {
        float4 r[2];
        loadA_regs(0, r);
        cpB(0, 0);
        CP_COMMIT();
        stsA(0, r);
        CP_WAIT0();
        __syncthreads();
    }
    // ---- main loop: 8 k-chunks ----
#pragma unroll 1
    for (int kc = 0; kc < 8; ++kc) {
        const int buf = kc & 1;
        float4 r[2];
        if (kc < 7) {
            cpB(kc + 1, buf ^ 1);
            CP_COMMIT();
            loadA_regs(kc + 1, r);
        }
        mma_buf(buf);
        if (kc < 7) {
            stsA(buf ^ 1, r);
            CP_WAIT0();
            __syncthreads();
        }
    }

    // ---- epilogue: C = scale*(acc + accq/4096 + bias) ----
    const float qs = 1.f / 4096.f;
#pragma unroll
    for (int mf = 0; mf < 2; ++mf) {
#pragma unroll
        for (int nf = 0; nf < 4; ++nf) {
            const int cn = wn * 32 + nf * 8 + tig * 2;
            const float b0 = sBias[cn], b1 = sBias[cn + 1];
            const long long r0 = m0 + wm * 32 + mf * 16 + g;
            float* p0 = C + r0 * N + n0 + cn;
            float* p1 = C + (r0 + 8) * N + n0 + cn;
            float v0 = acc[mf][nf][0] + accq[mf][nf][0] * qs;
            float v1 = acc[mf][nf][1] + accq[mf][nf][1] * qs;
            float v2 = acc[mf][nf][2] + accq[mf][nf][2] * qs;
            float v3 = acc[mf][nf][3] + accq[mf][nf][3] * qs;
            *reinterpret_cast<float2*>(p0) =
                make_float2(scale * (v0 + b0), scale * (v1 + b1));
            *reinterpret_cast<float2*>(p1) =
                make_float2(scale * (v2 + b0), scale * (v3 + b1));
        }
    }
}

// ---- attention: online softmax, register Q ----------------------------------
__global__ __launch_bounds__(64)
void attn_kernel() {
    __shared__ float sK[64][32];
    __shared__ float sV[64][32];
    __shared__ float sB[64][64];     // [m][n]

    const int w = blockIdx.x;
    const int h = blockIdx.y;
    const int tid = threadIdx.x;

    const float* kb = g_KV + (long long)w * (64 * 512) + h * 32;
    const float* vb = kb + 256;

#pragma unroll
    for (int it = 0; it < 8; ++it) {
        int idx = tid + it * 64;
        int row = idx >> 3;
        int cq  = (idx & 7) << 2;
        *reinterpret_cast<float4*>(&sK[row][cq]) =
            *reinterpret_cast<const float4*>(kb + row * 512 + cq);
        *reinterpret_cast<float4*>(&sV[row][cq]) =
            *reinterpret_cast<const float4*>(vb + row * 512 + cq);
    }
    const float* bb = g_bias + h * 4096;
#pragma unroll
    for (int it = 0; it < 16; ++it) {
        int idx = tid + it * 64;
        int m = idx >> 4, q = (idx & 15) << 2;
        *reinterpret_cast<float4*>(&sB[m][q]) =
            *reinterpret_cast<const float4*>(bb + m * 64 + q);
    }

    // Q row for this thread: 32 floats = 8 LDG.128
    const int n = tid;
    const float* qb = g_Q + (long long)w * (64 * 256) + n * 256 + h * 32;
    unsigned long long qp[16];
#pragma unroll
    for (int jj = 0; jj < 8; ++jj) {
        ulonglong2 v = *reinterpret_cast<const ulonglong2*>(qb + jj * 4);
        qp[jj * 2 + 0] = v.x;
        qp[jj * 2 + 1] = v.y;
    }
    __syncthreads();

    float mx = -1e30f, sum = 0.f;
    unsigned long long o2[16];
#pragma unroll
    for (int j = 0; j < 16; ++j) o2[j] = 0ull;

#pragma unroll 8
    for (int m = 0; m < 64; ++m) {
        unsigned long long acc = 0ull;
        const ulonglong2* k2 = reinterpret_cast<const ulonglong2*>(sK[m]);
#pragma unroll
        for (int jj = 0; jj < 8; ++jj) {
            ulonglong2 kk = k2[jj];
            fma2(acc, qp[jj * 2 + 0], kk.x);
            fma2(acc, qp[jj * 2 + 1], kk.y);
        }
        float lo, hi;
        unpk(acc, lo, hi);
        float s = lo + hi + sB[m][n];

        float p;
        if (s > mx) {
            float f = __expf(mx - s);      // 0 on first iteration
            mx = s;
            sum = sum * f + 1.f;
            unsigned long long f2 = pk2(f);
#pragma unroll
            for (int j = 0; j < 16; ++j) mul2(o2[j], f2);
            p = 1.f;
        } else {
            p = __expf(s - mx);
            sum += p;
        }
        unsigned long long pp = pk2(p);
        const ulonglong2* v2 = reinterpret_cast<const ulonglong2*>(sV[m]);
#pragma unroll
        for (int jj = 0; jj < 8; ++jj) {
            ulonglong2 vv = v2[jj];
            fma2(o2[jj * 2 + 0], pp, vv.x);
            fma2(o2[jj * 2 + 1], pp, vv.y);
        }
    }

    const float inv = 1.f / sum;
    float* ob = g_O + (long long)w * (64 * 256) + n * 256 + h * 32;
#pragma unroll
    for (int jq = 0; jq < 8; ++jq) {
        float a, b, c, d;
        unpk(o2[jq * 2 + 0], a, b);
        unpk(o2[jq * 2 + 1], c, d);
        *reinterpret_cast<float4*>(ob + jq * 4) =
            make_float4(a * inv, b * inv, c * inv, d * inv);
    }
}

// ---------------------------------------------------------------------------
extern "C" void kernel_launch(void* const* d_in, const int* in_sizes, int n_in,
                              void* d_out, int out_size) {
    const float* xq  = (const float*)d_in[0];
    const float* xs  = (const float*)d_in[1];
    const float* Wq  = (const float*)d_in[2];
    const float* bq  = (const float*)d_in[3];
    const float* Wkv = (const float*)d_in[4];
    const float* bkv = (const float*)d_in[5];
    const float* bt  = (const float*)d_in[6];
    const float* Wp  = (const float*)d_in[7];
    const float* bp  = (const float*)d_in[8];
    float* out = (float*)d_out;

    const int M = in_sizes[0] / 256;            // 262144
    const int B = M / 64;                       // 4096
    const float scale = 0.17677669529663687f;   // 32^-0.5

    cudaFuncSetAttribute(gemm_tc<256, 0, 0>,
                         cudaFuncAttributeMaxDynamicSharedMemorySize, GSM_TOTAL);
    cudaFuncSetAttribute(gemm_tc<512, 1, 0>,
                         cudaFuncAttributeMaxDynamicSharedMemorySize, GSM_TOTAL);
    cudaFuncSetAttribute(gemm_tc<256, 2, 1>,
                         cudaFuncAttributeMaxDynamicSharedMemorySize, GSM_TOTAL);

    bias_kernel<<<128, 256>>>(bt);

    convw_kernel<<<256, 256>>>(Wq, 256);
    gemm_tc<256, 0, 0><<<dim3(2, M / 128), 512, GSM_TOTAL>>>(xq, bq, nullptr, scale);

    convw_kernel<<<512, 256>>>(Wkv, 512);
    gemm_tc<512, 1, 0><<<dim3(4, M / 128), 512, GSM_TOTAL>>>(xs, bkv, nullptr, 1.f);

    attn_kernel<<<dim3(B, 8), 64>>>();

    convw_kernel<<<256, 256>>>(Wp, 256);
    gemm_tc<256, 2, 1><<<dim3(2, M / 128), 512, GSM_TOTAL>>>(nullptr, bp, out, 1.f);
}

// round 7
// speedup vs baseline: 1.4934x; 1.4934x over previous
#include <cuda_runtime.h>
#include <cuda_fp16.h>
#include <cuda_bf16.h>
#include <cstdint>

// ---------------------------------------------------------------------------
// WindowedCrossAttention — R7
//   GEMMs: 2-pass fp16 HMMA:  C = A16*Wh + A16*(Wl*4096)/4096
//     (A rounded once to fp16: RMS 2.1e-4; W split hi/lo fp16, precomputed)
//   Attention: R5's proven version (f32x2, __expf, transposed-bias LDG)
// ---------------------------------------------------------------------------

__device__ float g_Q [4096ull * 64ull * 256ull];
__device__ float g_KV[4096ull * 64ull * 512ull];
__device__ float g_O [4096ull * 64ull * 256ull];
__device__ float g_bias[8 * 64 * 64];                 // [h][m][n]
__device__ __half g_Wh[512 * 256];                    // fp16(W), [n][k]
__device__ __half g_Wl[512 * 256];                    // fp16((W - Wh) * 4096)

// ---- helpers ----------------------------------------------------------------
__device__ __forceinline__ uint32_t smem_u32(const void* p) {
    uint32_t a;
    asm("{ .reg .u64 t; cvta.to.shared.u64 t, %1; cvt.u32.u64 %0, t; }" : "=r"(a) : "l"(p));
    return a;
}
__device__ __forceinline__ unsigned long long pk2(float x) {
    unsigned long long r;
    asm("mov.b64 %0, {%1, %1};" : "=l"(r) : "r"(__float_as_uint(x)));
    return r;
}
__device__ __forceinline__ unsigned long long pkpair(float a, float b) {
    unsigned long long r;
    asm("mov.b64 %0, {%1, %2};" : "=l"(r) : "r"(__float_as_uint(a)), "r"(__float_as_uint(b)));
    return r;
}
__device__ __forceinline__ void fma2(unsigned long long& d, unsigned long long a,
                                     unsigned long long b) {
    asm("fma.rn.f32x2 %0, %1, %2, %0;" : "+l"(d) : "l"(a), "l"(b));
}
__device__ __forceinline__ void unpk(unsigned long long v, float& lo, float& hi) {
    unsigned int l, h;
    asm("mov.b64 {%0, %1}, %2;" : "=r"(l), "=r"(h) : "l"(v));
    lo = __uint_as_float(l);
    hi = __uint_as_float(h);
}
__device__ __forceinline__ void mma16816f16(float* c, const uint32_t* a, const uint32_t* b) {
    asm volatile(
        "mma.sync.aligned.m16n8k16.row.col.f32.f16.f16.f32 "
        "{%0,%1,%2,%3}, {%4,%5,%6,%7}, {%8,%9}, {%0,%1,%2,%3};"
        : "+f"(c[0]), "+f"(c[1]), "+f"(c[2]), "+f"(c[3])
        : "r"(a[0]), "r"(a[1]), "r"(a[2]), "r"(a[3]), "r"(b[0]), "r"(b[1]));
}
#define CP_ASYNC16(dst, src) \
    asm volatile("cp.async.cg.shared.global [%0], [%1], 16;" :: "r"(dst), "l"(src))
#define CP_COMMIT() asm volatile("cp.async.commit_group;")
#define CP_WAIT0()  asm volatile("cp.async.wait_group 0;")

// ---- relative-position bias (transposed [h][m][n]) ---------------------------
__global__ void bias_kernel(const float* __restrict__ bt) {
    int idx = blockIdx.x * 256 + threadIdx.x;
    if (idx >= 8 * 64 * 64) return;
    int h  = idx >> 12;
    int nm = idx & 4095;
    int m = nm >> 6, n = nm & 63;
    int dy = (n >> 3) - (m >> 3);
    int dx = (n & 7) - (m & 7);
    int r  = (dy + 7) * 15 + (dx + 7);
    g_bias[idx] = bt[r * 8 + h];
}

// ---- W -> fp16 hi + fp16 lo (residual * 4096), transposed [n][k] -------------
__global__ void convw_kernel(const float* __restrict__ W, int Ncols) {
    int idx = blockIdx.x * 256 + threadIdx.x;
    if (idx >= Ncols * 256) return;
    int n = idx >> 8;
    int k = idx & 255;
    float v = W[k * Ncols + n];
    __half h = __float2half_rn(v);
    g_Wh[idx] = h;
    g_Wl[idx] = __float2half_rn((v - __half2float(h)) * 4096.f);
}

// ---- fp16 GEMM:  C[M,N] = scale*(A[M,256] @ W + bias) ------------------------
// 512 threads, block 128x128, warp 32x32 (4x4), KC=32, ping-pong smem.
// Buffer (base = 1024 + buf*30720):  A16@0  Wh@10240  Wl@20480
//   each: 128 rows x 32 fp16, rows padded to 40 halves (80B).
#define GSM_TOTAL (1024 + 2 * 30720)
#define AS 40

template <int N, int DSTSEL, int SRCSEL>
__global__ __launch_bounds__(512, 1)
void gemm_tc(const float* __restrict__ Ap, const float* __restrict__ bias,
             float* __restrict__ Cp, float scale) {
    extern __shared__ __align__(1024) char smem[];
    const uint32_t sb = smem_u32(smem);

    const float* A = (SRCSEL == 0) ? Ap : g_O;
    float* C = (DSTSEL == 0) ? g_Q : ((DSTSEL == 1) ? g_KV : Cp);

    const int tid  = threadIdx.x;
    const int wid  = tid >> 5, lane = tid & 31;
    const int g    = lane >> 2, tig = lane & 3;
    const int wm   = wid & 3, wn = wid >> 2;
    const int n0   = blockIdx.x * 128;
    const long long m0 = (long long)blockIdx.y * 128;

    float* sBias = (float*)smem;
    if (tid < 128) sBias[tid] = bias[n0 + tid];

    float acc[2][4][4];      // A * Wh
    float accq[2][4][4];     // A * (Wl*4096)
#pragma unroll
    for (int i = 0; i < 2; ++i)
#pragma unroll
        for (int j = 0; j < 4; ++j)
#pragma unroll
            for (int q = 0; q < 4; ++q) { acc[i][j][q] = 0.f; accq[i][j][q] = 0.f; }

    // ---- loaders ----
    auto loadA_regs = [&](int kc, float4* r) {
#pragma unroll
        for (int i = 0; i < 2; ++i) {
            int idx = tid + i * 512;
            int row = idx >> 3;
            int q = idx & 7;
            r[i] = *reinterpret_cast<const float4*>(
                A + (m0 + row) * 256 + kc * 32 + q * 4);
        }
    };
    auto stsA = [&](int buf, const float4* r) {
        char* base = smem + 1024 + buf * 30720;
#pragma unroll
        for (int i = 0; i < 2; ++i) {
            int idx = tid + i * 512;
            int row = idx >> 3;
            int q = idx & 7;
            float4 v = r[i];
            __half2 p0 = __floats2half2_rn(v.x, v.y);
            __half2 p1 = __floats2half2_rn(v.z, v.w);
            *reinterpret_cast<uint2*>(base + row * 80 + q * 8) =
                make_uint2(*reinterpret_cast<uint32_t*>(&p0),
                           *reinterpret_cast<uint32_t*>(&p1));
        }
    };
    auto cpB = [&](int kc, int buf) {
        uint32_t base = sb + 1024 + buf * 30720;
        int row = tid >> 2, seg = tid & 3;
        const __half* sh = g_Wh + (long long)(n0 + row) * 256 + kc * 32 + seg * 8;
        const __half* sl = g_Wl + (long long)(n0 + row) * 256 + kc * 32 + seg * 8;
        CP_ASYNC16(base + 10240 + row * 80 + seg * 16, sh);
        CP_ASYNC16(base + 20480 + row * 80 + seg * 16, sl);
    };
    auto mma_buf = [&](int buf) {
        const __half* Aw = (const __half*)(smem + 1024 + buf * 30720);
        const __half* Bh = Aw + 5120;
        const __half* Bl = Aw + 10240;
#pragma unroll
        for (int ks = 0; ks < 2; ++ks) {
            const int k0 = ks * 16;
            uint32_t af[2][4], bh[4][2], bl[4][2];
#pragma unroll
            for (int mf = 0; mf < 2; ++mf) {
                const __half* p = Aw + (wm * 32 + mf * 16 + g) * AS + k0 + tig * 2;
                af[mf][0] = *(const uint32_t*)p;
                af[mf][1] = *(const uint32_t*)(p + 8 * AS);
                af[mf][2] = *(const uint32_t*)(p + 8);
                af[mf][3] = *(const uint32_t*)(p + 8 * AS + 8);
            }
#pragma unroll
            for (int nf = 0; nf < 4; ++nf) {
                const __half* p = Bh + (wn * 32 + nf * 8 + g) * AS + k0 + tig * 2;
                const __half* q = Bl + (wn * 32 + nf * 8 + g) * AS + k0 + tig * 2;
                bh[nf][0] = *(const uint32_t*)p;
                bh[nf][1] = *(const uint32_t*)(p + 8);
                bl[nf][0] = *(const uint32_t*)q;
                bl[nf][1] = *(const uint32_t*)(q + 8);
            }
#pragma unroll
            for (int mf = 0; mf < 2; ++mf)
#pragma unroll
                for (int nf = 0; nf < 4; ++nf) {
                    mma16816f16(acc[mf][nf],  af[mf], bh[nf]);
                    mma16816f16(accq[mf][nf], af[mf], bl[nf]);
                }
        }
    };

    // ---- prologue: chunk 0 ----
    {
        float4 r[2];
        loadA_regs(0, r);
        cpB(0, 0);
        CP_COMMIT();
        stsA(0, r);
        CP_WAIT0();
        __syncthreads();
    }
    // ---- main loop: 8 k-chunks ----
#pragma unroll 1
    for (int kc = 0; kc < 8; ++kc) {
        const int buf = kc & 1;
        float4 r[2];
        if (kc < 7) {
            cpB(kc + 1, buf ^ 1);
            CP_COMMIT();
            loadA_regs(kc + 1, r);
        }
        mma_buf(buf);
        if (kc < 7) {
            stsA(buf ^ 1, r);
            CP_WAIT0();
            __syncthreads();
        }
    }

    // ---- epilogue: C = scale*(acc + accq/4096 + bias) ----
    const float qs = 1.f / 4096.f;
#pragma unroll
    for (int mf = 0; mf < 2; ++mf) {
#pragma unroll
        for (int nf = 0; nf < 4; ++nf) {
            const int cn = wn * 32 + nf * 8 + tig * 2;
            const float b0 = sBias[cn], b1 = sBias[cn + 1];
            const long long r0 = m0 + wm * 32 + mf * 16 + g;
            float* p0 = C + r0 * N + n0 + cn;
            float* p1 = C + (r0 + 8) * N + n0 + cn;
            float v0 = acc[mf][nf][0] + accq[mf][nf][0] * qs;
            float v1 = acc[mf][nf][1] + accq[mf][nf][1] * qs;
            float v2 = acc[mf][nf][2] + accq[mf][nf][2] * qs;
            float v3 = acc[mf][nf][3] + accq[mf][nf][3] * qs;
            *reinterpret_cast<float2*>(p0) =
                make_float2(scale * (v0 + b0), scale * (v1 + b1));
            *reinterpret_cast<float2*>(p1) =
                make_float2(scale * (v2 + b0), scale * (v3 + b1));
        }
    }
}

// ---- fused attention per (window, head) — R5 proven version -------------------
__global__ __launch_bounds__(64)
void attn_kernel() {
    __shared__ float sQ[64][33];
    __shared__ float sK[64][32];
    __shared__ float sV[64][32];

    const int w = blockIdx.x;
    const int h = blockIdx.y;
    const int tid = threadIdx.x;

    const float* qb = g_Q  + (long long)w * (64 * 256) + h * 32;
    const float* kb = g_KV + (long long)w * (64 * 512) + h * 32;
    const float* vb = kb + 256;

#pragma unroll
    for (int it = 0; it < 8; ++it) {
        int idx = tid + it * 64;
        int row = idx >> 3;
        int cq  = (idx & 7) << 2;
        float4 qv = *reinterpret_cast<const float4*>(qb + row * 256 + cq);
        sQ[row][cq + 0] = qv.x; sQ[row][cq + 1] = qv.y;
        sQ[row][cq + 2] = qv.z; sQ[row][cq + 3] = qv.w;
        *reinterpret_cast<float4*>(&sK[row][cq]) =
            *reinterpret_cast<const float4*>(kb + row * 512 + cq);
        *reinterpret_cast<float4*>(&sV[row][cq]) =
            *reinterpret_cast<const float4*>(vb + row * 512 + cq);
    }
    __syncthreads();

    const int n = tid;
    const float* bT = g_bias + h * 4096 + n;   // [h][m][n]: coalesced over n
    float s[64];
#pragma unroll
    for (int m = 0; m < 64; ++m) s[m] = bT[m * 64];

    unsigned long long qp[16];
#pragma unroll
    for (int j = 0; j < 16; ++j) qp[j] = pkpair(sQ[n][2 * j], sQ[n][2 * j + 1]);

#pragma unroll
    for (int m = 0; m < 64; ++m) {
        const unsigned long long* kr = reinterpret_cast<const unsigned long long*>(sK[m]);
        unsigned long long acc = 0ull;
#pragma unroll
        for (int j = 0; j < 16; ++j) fma2(acc, qp[j], kr[j]);
        float lo, hi;
        unpk(acc, lo, hi);
        s[m] += lo + hi;
    }

    float mx = s[0];
#pragma unroll
    for (int m = 1; m < 64; ++m) mx = fmaxf(mx, s[m]);
    float sum = 0.f;
#pragma unroll
    for (int m = 0; m < 64; ++m) {
        s[m] = __expf(s[m] - mx);
        sum += s[m];
    }
    const float inv = 1.f / sum;

    unsigned long long o2[16];
#pragma unroll
    for (int j = 0; j < 16; ++j) o2[j] = 0ull;
#pragma unroll
    for (int m = 0; m < 64; ++m) {
        const unsigned long long* vr = reinterpret_cast<const unsigned long long*>(sV[m]);
        unsigned long long p = pk2(s[m]);
#pragma unroll
        for (int j = 0; j < 16; ++j) fma2(o2[j], p, vr[j]);
    }

    float* ob = g_O + (long long)w * (64 * 256) + n * 256 + h * 32;
#pragma unroll
    for (int jq = 0; jq < 8; ++jq) {
        float a, b, c, d;
        unpk(o2[jq * 2 + 0], a, b);
        unpk(o2[jq * 2 + 1], c, d);
        *reinterpret_cast<float4*>(ob + jq * 4) =
            make_float4(a * inv, b * inv, c * inv, d * inv);
    }
}

// ---------------------------------------------------------------------------
extern "C" void kernel_launch(void* const* d_in, const int* in_sizes, int n_in,
                              void* d_out, int out_size) {
    const float* xq  = (const float*)d_in[0];
    const float* xs  = (const float*)d_in[1];
    const float* Wq  = (const float*)d_in[2];
    const float* bq  = (const float*)d_in[3];
    const float* Wkv = (const float*)d_in[4];
    const float* bkv = (const float*)d_in[5];
    const float* bt  = (const float*)d_in[6];
    const float* Wp  = (const float*)d_in[7];
    const float* bp  = (const float*)d_in[8];
    float* out = (float*)d_out;

    const int M = in_sizes[0] / 256;            // 262144
    const int B = M / 64;                       // 4096
    const float scale = 0.17677669529663687f;   // 32^-0.5

    cudaFuncSetAttribute(gemm_tc<256, 0, 0>,
                         cudaFuncAttributeMaxDynamicSharedMemorySize, GSM_TOTAL);
    cudaFuncSetAttribute(gemm_tc<512, 1, 0>,
                         cudaFuncAttributeMaxDynamicSharedMemorySize, GSM_TOTAL);
    cudaFuncSetAttribute(gemm_tc<256, 2, 1>,
                         cudaFuncAttributeMaxDynamicSharedMemorySize, GSM_TOTAL);

    bias_kernel<<<128, 256>>>(bt);

    convw_kernel<<<256, 256>>>(Wq, 256);
    gemm_tc<256, 0, 0><<<dim3(2, M / 128), 512, GSM_TOTAL>>>(xq, bq, nullptr, scale);

    convw_kernel<<<512, 256>>>(Wkv, 512);
    gemm_tc<512, 1, 0><<<dim3(4, M / 128), 512, GSM_TOTAL>>>(xs, bkv, nullptr, 1.f);

    attn_kernel<<<dim3(B, 8), 64>>>();

    convw_kernel<<<256, 256>>>(Wp, 256);
    gemm_tc<256, 2, 1><<<dim3(2, M / 128), 512, GSM_TOTAL>>>(nullptr, bp, out, 1.f);
}

// round 8
// speedup vs baseline: 1.8419x; 1.2334x over previous
#include <cuda_runtime.h>
#include <cuda_fp16.h>
#include <cstdint>

// ---------------------------------------------------------------------------
// WindowedCrossAttention — R8
//   GEMMs: R7 2-pass fp16 HMMA (C = A16*Wh + A16*(Wl*4096)/4096)  [unchanged]
//   Attention: fp16 HMMA per window. Block = 1 window (512 thr, 16 warps);
//     warp (h, mhalf) does 32 query rows: S = Q K^T + bias (fp32 accum),
//     row softmax in registers, P repacked in-register as A-frags, O = P V.
// ---------------------------------------------------------------------------

__device__ float g_Q [4096ull * 64ull * 256ull];
__device__ float g_KV[4096ull * 64ull * 512ull];
__device__ float g_O [4096ull * 64ull * 256ull];
__device__ float g_bias[8 * 64 * 64];                 // [h][q][k]
__device__ __half g_Wh[512 * 256];                    // fp16(W), [n][k]
__device__ __half g_Wl[512 * 256];                    // fp16((W - Wh) * 4096)

// ---- helpers ----------------------------------------------------------------
__device__ __forceinline__ uint32_t smem_u32(const void* p) {
    uint32_t a;
    asm("{ .reg .u64 t; cvta.to.shared.u64 t, %1; cvt.u32.u64 %0, t; }" : "=r"(a) : "l"(p));
    return a;
}
__device__ __forceinline__ void mma16816f16(float* c, const uint32_t* a, const uint32_t* b) {
    asm volatile(
        "mma.sync.aligned.m16n8k16.row.col.f32.f16.f16.f32 "
        "{%0,%1,%2,%3}, {%4,%5,%6,%7}, {%8,%9}, {%0,%1,%2,%3};"
        : "+f"(c[0]), "+f"(c[1]), "+f"(c[2]), "+f"(c[3])
        : "r"(a[0]), "r"(a[1]), "r"(a[2]), "r"(a[3]), "r"(b[0]), "r"(b[1]));
}
__device__ __forceinline__ uint32_t h2pack(float a, float b) {
    __half2 h = __floats2half2_rn(a, b);
    return *reinterpret_cast<uint32_t*>(&h);
}
#define CP_ASYNC16(dst, src) \
    asm volatile("cp.async.cg.shared.global [%0], [%1], 16;" :: "r"(dst), "l"(src))
#define CP_COMMIT() asm volatile("cp.async.commit_group;")
#define CP_WAIT0()  asm volatile("cp.async.wait_group 0;")

// ---- relative-position bias: g_bias[h][q][k] = bt[rel(q,k)][h] ---------------
__global__ void bias_kernel(const float* __restrict__ bt) {
    int idx = blockIdx.x * 256 + threadIdx.x;
    if (idx >= 8 * 64 * 64) return;
    int h  = idx >> 12;
    int nm = idx & 4095;
    int q = nm >> 6, k = nm & 63;
    int dy = (q >> 3) - (k >> 3);
    int dx = (q & 7) - (k & 7);
    int r  = (dy + 7) * 15 + (dx + 7);
    g_bias[idx] = bt[r * 8 + h];
}

// ---- W -> fp16 hi + fp16 lo (residual * 4096), transposed [n][k] -------------
__global__ void convw_kernel(const float* __restrict__ W, int Ncols) {
    int idx = blockIdx.x * 256 + threadIdx.x;
    if (idx >= Ncols * 256) return;
    int n = idx >> 8;
    int k = idx & 255;
    float v = W[k * Ncols + n];
    __half h = __float2half_rn(v);
    g_Wh[idx] = h;
    g_Wl[idx] = __float2half_rn((v - __half2float(h)) * 4096.f);
}

// ---- fp16 GEMM (R7, unchanged) -----------------------------------------------
#define GSM_TOTAL (1024 + 2 * 30720)
#define AS 40

template <int N, int DSTSEL, int SRCSEL>
__global__ __launch_bounds__(512, 1)
void gemm_tc(const float* __restrict__ Ap, const float* __restrict__ bias,
             float* __restrict__ Cp, float scale) {
    extern __shared__ __align__(1024) char smem[];
    const uint32_t sb = smem_u32(smem);

    const float* A = (SRCSEL == 0) ? Ap : g_O;
    float* C = (DSTSEL == 0) ? g_Q : ((DSTSEL == 1) ? g_KV : Cp);

    const int tid  = threadIdx.x;
    const int wid  = tid >> 5, lane = tid & 31;
    const int g    = lane >> 2, tig = lane & 3;
    const int wm   = wid & 3, wn = wid >> 2;
    const int n0   = blockIdx.x * 128;
    const long long m0 = (long long)blockIdx.y * 128;

    float* sBias = (float*)smem;
    if (tid < 128) sBias[tid] = bias[n0 + tid];

    float acc[2][4][4];
    float accq[2][4][4];
#pragma unroll
    for (int i = 0; i < 2; ++i)
#pragma unroll
        for (int j = 0; j < 4; ++j)
#pragma unroll
            for (int q = 0; q < 4; ++q) { acc[i][j][q] = 0.f; accq[i][j][q] = 0.f; }

    auto loadA_regs = [&](int kc, float4* r) {
#pragma unroll
        for (int i = 0; i < 2; ++i) {
            int idx = tid + i * 512;
            int row = idx >> 3;
            int q = idx & 7;
            r[i] = *reinterpret_cast<const float4*>(
                A + (m0 + row) * 256 + kc * 32 + q * 4);
        }
    };
    auto stsA = [&](int buf, const float4* r) {
        char* base = smem + 1024 + buf * 30720;
#pragma unroll
        for (int i = 0; i < 2; ++i) {
            int idx = tid + i * 512;
            int row = idx >> 3;
            int q = idx & 7;
            float4 v = r[i];
            __half2 p0 = __floats2half2_rn(v.x, v.y);
            __half2 p1 = __floats2half2_rn(v.z, v.w);
            *reinterpret_cast<uint2*>(base + row * 80 + q * 8) =
                make_uint2(*reinterpret_cast<uint32_t*>(&p0),
                           *reinterpret_cast<uint32_t*>(&p1));
        }
    };
    auto cpB = [&](int kc, int buf) {
        uint32_t base = sb + 1024 + buf * 30720;
        int row = tid >> 2, seg = tid & 3;
        const __half* sh = g_Wh + (long long)(n0 + row) * 256 + kc * 32 + seg * 8;
        const __half* sl = g_Wl + (long long)(n0 + row) * 256 + kc * 32 + seg * 8;
        CP_ASYNC16(base + 10240 + row * 80 + seg * 16, sh);
        CP_ASYNC16(base + 20480 + row * 80 + seg * 16, sl);
    };
    auto mma_buf = [&](int buf) {
        const __half* Aw = (const __half*)(smem + 1024 + buf * 30720);
        const __half* Bh = Aw + 5120;
        const __half* Bl = Aw + 10240;
#pragma unroll
        for (int ks = 0; ks < 2; ++ks) {
            const int k0 = ks * 16;
            uint32_t af[2][4], bh[4][2], bl[4][2];
#pragma unroll
            for (int mf = 0; mf < 2; ++mf) {
                const __half* p = Aw + (wm * 32 + mf * 16 + g) * AS + k0 + tig * 2;
                af[mf][0] = *(const uint32_t*)p;
                af[mf][1] = *(const uint32_t*)(p + 8 * AS);
                af[mf][2] = *(const uint32_t*)(p + 8);
                af[mf][3] = *(const uint32_t*)(p + 8 * AS + 8);
            }
#pragma unroll
            for (int nf = 0; nf < 4; ++nf) {
                const __half* p = Bh + (wn * 32 + nf * 8 + g) * AS + k0 + tig * 2;
                const __half* q = Bl + (wn * 32 + nf * 8 + g) * AS + k0 + tig * 2;
                bh[nf][0] = *(const uint32_t*)p;
                bh[nf][1] = *(const uint32_t*)(p + 8);
                bl[nf][0] = *(const uint32_t*)q;
                bl[nf][1] = *(const uint32_t*)(q + 8);
            }
#pragma unroll
            for (int mf = 0; mf < 2; ++mf)
#pragma unroll
                for (int nf = 0; nf < 4; ++nf) {
                    mma16816f16(acc[mf][nf],  af[mf], bh[nf]);
                    mma16816f16(accq[mf][nf], af[mf], bl[nf]);
                }
        }
    };

    {
        float4 r[2];
        loadA_regs(0, r);
        cpB(0, 0);
        CP_COMMIT();
        stsA(0, r);
        CP_WAIT0();
        __syncthreads();
    }
#pragma unroll 1
    for (int kc = 0; kc < 8; ++kc) {
        const int buf = kc & 1;
        float4 r[2];
        if (kc < 7) {
            cpB(kc + 1, buf ^ 1);
            CP_COMMIT();
            loadA_regs(kc + 1, r);
        }
        mma_buf(buf);
        if (kc < 7) {
            stsA(buf ^ 1, r);
            CP_WAIT0();
            __syncthreads();
        }
    }

    const float qs = 1.f / 4096.f;
#pragma unroll
    for (int mf = 0; mf < 2; ++mf) {
#pragma unroll
        for (int nf = 0; nf < 4; ++nf) {
            const int cn = wn * 32 + nf * 8 + tig * 2;
            const float b0 = sBias[cn], b1 = sBias[cn + 1];
            const long long r0 = m0 + wm * 32 + mf * 16 + g;
            float* p0 = C + r0 * N + n0 + cn;
            float* p1 = C + (r0 + 8) * N + n0 + cn;
            float v0 = acc[mf][nf][0] + accq[mf][nf][0] * qs;
            float v1 = acc[mf][nf][1] + accq[mf][nf][1] * qs;
            float v2 = acc[mf][nf][2] + accq[mf][nf][2] * qs;
            float v3 = acc[mf][nf][3] + accq[mf][nf][3] * qs;
            *reinterpret_cast<float2*>(p0) =
                make_float2(scale * (v0 + b0), scale * (v1 + b1));
            *reinterpret_cast<float2*>(p1) =
                make_float2(scale * (v2 + b0), scale * (v3 + b1));
        }
    }
}

// ---- attention via fp16 HMMA: block = 1 window -------------------------------
// smem: sK [8][64][40] halves (40960 B) + sVt [8][32][72] halves (36864 B)
#define ASM_TOTAL (40960 + 36864)

__global__ __launch_bounds__(512, 1)
void attn_mma() {
    extern __shared__ __align__(16) char smem[];
    __half* sK  = (__half*)smem;                 // [h][key][40]
    __half* sVt = (__half*)(smem + 40960);       // [h][d][72]

    const int w = blockIdx.x;
    const int tid = threadIdx.x;
    const float* kvb = g_KV + (long long)w * 32768;

    // ---- stage K (fp16) and V (fp16, transposed) ----
#pragma unroll
    for (int i = 0; i < 8; ++i) {
        int idx = tid + i * 512;                 // 0..4095 float4-units
        int h   = idx >> 9;
        int rem = idx & 511;
        int key = rem >> 3;
        int dq  = (rem & 7) << 2;
        const float* kp = kvb + key * 512 + h * 32 + dq;
        float4 k4 = *reinterpret_cast<const float4*>(kp);
        __half2 k01 = __floats2half2_rn(k4.x, k4.y);
        __half2 k23 = __floats2half2_rn(k4.z, k4.w);
        *reinterpret_cast<uint2*>(sK + h * 2560 + key * 40 + dq) =
            make_uint2(*reinterpret_cast<uint32_t*>(&k01),
                       *reinterpret_cast<uint32_t*>(&k23));
        float4 v4 = *reinterpret_cast<const float4*>(kp + 256);
        __half* vt = sVt + h * 2304 + key;
        vt[(dq + 0) * 72] = __float2half_rn(v4.x);
        vt[(dq + 1) * 72] = __float2half_rn(v4.y);
        vt[(dq + 2) * 72] = __float2half_rn(v4.z);
        vt[(dq + 3) * 72] = __float2half_rn(v4.w);
    }
    __syncthreads();

    const int wid = tid >> 5, lane = tid & 31;
    const int g = lane >> 2, t = lane & 3;
    const int h = wid >> 1, mh = wid & 1;        // warp: head h, query half mh
    const __half* Kh = sK + h * 2560;
    const __half* Vh = sVt + h * 2304;

    // ---- Q fragments (fp32 gmem -> fp16 regs) ----
    uint32_t qf[2][2][4];                        // [mt][kb][reg]
    const float* qbase = g_Q + (long long)w * 16384 + h * 32;
#pragma unroll
    for (int mt = 0; mt < 2; ++mt) {
        const int R = (mh * 2 + mt) * 16 + g;
#pragma unroll
        for (int kb = 0; kb < 2; ++kb) {
            const int c = kb * 16 + t * 2;
            float2 v0 = *reinterpret_cast<const float2*>(qbase + R * 256 + c);
            float2 v1 = *reinterpret_cast<const float2*>(qbase + (R + 8) * 256 + c);
            float2 v2 = *reinterpret_cast<const float2*>(qbase + R * 256 + c + 8);
            float2 v3 = *reinterpret_cast<const float2*>(qbase + (R + 8) * 256 + c + 8);
            qf[mt][kb][0] = h2pack(v0.x, v0.y);
            qf[mt][kb][1] = h2pack(v1.x, v1.y);
            qf[mt][kb][2] = h2pack(v2.x, v2.y);
            qf[mt][kb][3] = h2pack(v3.x, v3.y);
        }
    }

    // ---- S = Q K^T (fp32 accum) ----
    float S[2][8][4];
#pragma unroll
    for (int mt = 0; mt < 2; ++mt)
#pragma unroll
        for (int nb = 0; nb < 8; ++nb)
#pragma unroll
            for (int q = 0; q < 4; ++q) S[mt][nb][q] = 0.f;

#pragma unroll
    for (int nb = 0; nb < 8; ++nb) {
        uint32_t bf[2][2];
#pragma unroll
        for (int kb = 0; kb < 2; ++kb) {
            const __half* p = Kh + (8 * nb + g) * 40 + kb * 16 + t * 2;
            bf[kb][0] = *(const uint32_t*)p;
            bf[kb][1] = *(const uint32_t*)(p + 8);
        }
#pragma unroll
        for (int mt = 0; mt < 2; ++mt)
#pragma unroll
            for (int kb = 0; kb < 2; ++kb)
                mma16816f16(S[mt][nb], qf[mt][kb], bf[kb]);
    }

    // ---- + bias ----
    const float* bb = g_bias + h * 4096;
#pragma unroll
    for (int mt = 0; mt < 2; ++mt) {
        const int R = (mh * 2 + mt) * 16 + g;
#pragma unroll
        for (int nb = 0; nb < 8; ++nb) {
            const int c = nb * 8 + t * 2;
            float2 b0 = *reinterpret_cast<const float2*>(bb + R * 64 + c);
            float2 b1 = *reinterpret_cast<const float2*>(bb + (R + 8) * 64 + c);
            S[mt][nb][0] += b0.x; S[mt][nb][1] += b0.y;
            S[mt][nb][2] += b1.x; S[mt][nb][3] += b1.y;
        }
    }

    // ---- row softmax (rows g and g+8 per mt) ----
    float inv[2][2];
#pragma unroll
    for (int mt = 0; mt < 2; ++mt) {
        float m0 = -1e30f, m1 = -1e30f;
#pragma unroll
        for (int nb = 0; nb < 8; ++nb) {
            m0 = fmaxf(m0, fmaxf(S[mt][nb][0], S[mt][nb][1]));
            m1 = fmaxf(m1, fmaxf(S[mt][nb][2], S[mt][nb][3]));
        }
        m0 = fmaxf(m0, __shfl_xor_sync(0xFFFFFFFF, m0, 1));
        m0 = fmaxf(m0, __shfl_xor_sync(0xFFFFFFFF, m0, 2));
        m1 = fmaxf(m1, __shfl_xor_sync(0xFFFFFFFF, m1, 1));
        m1 = fmaxf(m1, __shfl_xor_sync(0xFFFFFFFF, m1, 2));
        float s0 = 0.f, s1 = 0.f;
#pragma unroll
        for (int nb = 0; nb < 8; ++nb) {
            S[mt][nb][0] = __expf(S[mt][nb][0] - m0);
            S[mt][nb][1] = __expf(S[mt][nb][1] - m0);
            S[mt][nb][2] = __expf(S[mt][nb][2] - m1);
            S[mt][nb][3] = __expf(S[mt][nb][3] - m1);
            s0 += S[mt][nb][0] + S[mt][nb][1];
            s1 += S[mt][nb][2] + S[mt][nb][3];
        }
        s0 += __shfl_xor_sync(0xFFFFFFFF, s0, 1);
        s0 += __shfl_xor_sync(0xFFFFFFFF, s0, 2);
        s1 += __shfl_xor_sync(0xFFFFFFFF, s1, 1);
        s1 += __shfl_xor_sync(0xFFFFFFFF, s1, 2);
        inv[mt][0] = 1.f / s0;
        inv[mt][1] = 1.f / s1;
    }

    // ---- repack P (unnormalized) into A-fragments (pure register) ----
    uint32_t pf[2][4][4];                        // [mt][kb][reg]
#pragma unroll
    for (int mt = 0; mt < 2; ++mt)
#pragma unroll
        for (int kb = 0; kb < 4; ++kb) {
            pf[mt][kb][0] = h2pack(S[mt][2 * kb][0],     S[mt][2 * kb][1]);
            pf[mt][kb][1] = h2pack(S[mt][2 * kb][2],     S[mt][2 * kb][3]);
            pf[mt][kb][2] = h2pack(S[mt][2 * kb + 1][0], S[mt][2 * kb + 1][1]);
            pf[mt][kb][3] = h2pack(S[mt][2 * kb + 1][2], S[mt][2 * kb + 1][3]);
        }

    // ---- O = P V ----
    float O[2][4][4];
#pragma unroll
    for (int mt = 0; mt < 2; ++mt)
#pragma unroll
        for (int nb = 0; nb < 4; ++nb)
#pragma unroll
            for (int q = 0; q < 4; ++q) O[mt][nb][q] = 0.f;

#pragma unroll
    for (int nb = 0; nb < 4; ++nb) {
        uint32_t vf[4][2];
#pragma unroll
        for (int kb = 0; kb < 4; ++kb) {
            const __half* p = Vh + (8 * nb + g) * 72 + kb * 16 + t * 2;
            vf[kb][0] = *(const uint32_t*)p;
            vf[kb][1] = *(const uint32_t*)(p + 8);
        }
#pragma unroll
        for (int mt = 0; mt < 2; ++mt)
#pragma unroll
            for (int kb = 0; kb < 4; ++kb)
                mma16816f16(O[mt][nb], pf[mt][kb], vf[kb]);
    }

    // ---- normalize + store ----
    float* ob = g_O + (long long)w * 16384 + h * 32;
#pragma unroll
    for (int mt = 0; mt < 2; ++mt) {
        const int R = (mh * 2 + mt) * 16 + g;
#pragma unroll
        for (int nb = 0; nb < 4; ++nb) {
            const int c = nb * 8 + t * 2;
            *reinterpret_cast<float2*>(ob + R * 256 + c) =
                make_float2(O[mt][nb][0] * inv[mt][0], O[mt][nb][1] * inv[mt][0]);
            *reinterpret_cast<float2*>(ob + (R + 8) * 256 + c) =
                make_float2(O[mt][nb][2] * inv[mt][1], O[mt][nb][3] * inv[mt][1]);
        }
    }
}

// ---------------------------------------------------------------------------
extern "C" void kernel_launch(void* const* d_in, const int* in_sizes, int n_in,
                              void* d_out, int out_size) {
    const float* xq  = (const float*)d_in[0];
    const float* xs  = (const float*)d_in[1];
    const float* Wq  = (const float*)d_in[2];
    const float* bq  = (const float*)d_in[3];
    const float* Wkv = (const float*)d_in[4];
    const float* bkv = (const float*)d_in[5];
    const float* bt  = (const float*)d_in[6];
    const float* Wp  = (const float*)d_in[7];
    const float* bp  = (const float*)d_in[8];
    float* out = (float*)d_out;

    const int M = in_sizes[0] / 256;            // 262144
    const int B = M / 64;                       // 4096
    const float scale = 0.17677669529663687f;   // 32^-0.5

    cudaFuncSetAttribute(gemm_tc<256, 0, 0>,
                         cudaFuncAttributeMaxDynamicSharedMemorySize, GSM_TOTAL);
    cudaFuncSetAttribute(gemm_tc<512, 1, 0>,
                         cudaFuncAttributeMaxDynamicSharedMemorySize, GSM_TOTAL);
    cudaFuncSetAttribute(gemm_tc<256, 2, 1>,
                         cudaFuncAttributeMaxDynamicSharedMemorySize, GSM_TOTAL);
    cudaFuncSetAttribute(attn_mma,
                         cudaFuncAttributeMaxDynamicSharedMemorySize, ASM_TOTAL);

    bias_kernel<<<128, 256>>>(bt);

    convw_kernel<<<256, 256>>>(Wq, 256);
    gemm_tc<256, 0, 0><<<dim3(2, M / 128), 512, GSM_TOTAL>>>(xq, bq, nullptr, scale);

    convw_kernel<<<512, 256>>>(Wkv, 512);
    gemm_tc<512, 1, 0><<<dim3(4, M / 128), 512, GSM_TOTAL>>>(xs, bkv, nullptr, 1.f);

    attn_mma<<<B, 512, ASM_TOTAL>>>();

    convw_kernel<<<256, 256>>>(Wp, 256);
    gemm_tc<256, 2, 1><<<dim3(2, M / 128), 512, GSM_TOTAL>>>(nullptr, bp, out, 1.f);
}

// round 9
// speedup vs baseline: 2.1426x; 1.1633x over previous
#include <cuda_runtime.h>
#include <cuda_fp16.h>
#include <cstdint>

// ---------------------------------------------------------------------------
// WindowedCrossAttention — R9
//   GEMMs: SINGLE-pass fp16 HMMA (A and W both fp16-rounded; err model 5e-4)
//   Attention: R8 fp16 HMMA per-window kernel (unchanged)
// ---------------------------------------------------------------------------

__device__ float g_Q [4096ull * 64ull * 256ull];
__device__ float g_KV[4096ull * 64ull * 512ull];
__device__ float g_O [4096ull * 64ull * 256ull];
__device__ float g_bias[8 * 64 * 64];                 // [h][q][k]
__device__ __half g_Wh[512 * 256];                    // fp16(W), [n][k]

// ---- helpers ----------------------------------------------------------------
__device__ __forceinline__ uint32_t smem_u32(const void* p) {
    uint32_t a;
    asm("{ .reg .u64 t; cvta.to.shared.u64 t, %1; cvt.u32.u64 %0, t; }" : "=r"(a) : "l"(p));
    return a;
}
__device__ __forceinline__ void mma16816f16(float* c, const uint32_t* a, const uint32_t* b) {
    asm volatile(
        "mma.sync.aligned.m16n8k16.row.col.f32.f16.f16.f32 "
        "{%0,%1,%2,%3}, {%4,%5,%6,%7}, {%8,%9}, {%0,%1,%2,%3};"
        : "+f"(c[0]), "+f"(c[1]), "+f"(c[2]), "+f"(c[3])
        : "r"(a[0]), "r"(a[1]), "r"(a[2]), "r"(a[3]), "r"(b[0]), "r"(b[1]));
}
__device__ __forceinline__ uint32_t h2pack(float a, float b) {
    __half2 h = __floats2half2_rn(a, b);
    return *reinterpret_cast<uint32_t*>(&h);
}
#define CP_ASYNC16(dst, src) \
    asm volatile("cp.async.cg.shared.global [%0], [%1], 16;" :: "r"(dst), "l"(src))
#define CP_COMMIT() asm volatile("cp.async.commit_group;")
#define CP_WAIT0()  asm volatile("cp.async.wait_group 0;")

// ---- relative-position bias: g_bias[h][q][k] = bt[rel(q,k)][h] ---------------
__global__ void bias_kernel(const float* __restrict__ bt) {
    int idx = blockIdx.x * 256 + threadIdx.x;
    if (idx >= 8 * 64 * 64) return;
    int h  = idx >> 12;
    int nm = idx & 4095;
    int q = nm >> 6, k = nm & 63;
    int dy = (q >> 3) - (k >> 3);
    int dx = (q & 7) - (k & 7);
    int r  = (dy + 7) * 15 + (dx + 7);
    g_bias[idx] = bt[r * 8 + h];
}

// ---- W -> fp16, transposed [n][k] --------------------------------------------
__global__ void convw_kernel(const float* __restrict__ W, int Ncols) {
    int idx = blockIdx.x * 256 + threadIdx.x;
    if (idx >= Ncols * 256) return;
    int n = idx >> 8;
    int k = idx & 255;
    g_Wh[idx] = __float2half_rn(W[k * Ncols + n]);
}

// ---- single-pass fp16 GEMM:  C[M,N] = scale*(A[M,256] @ W + bias) -------------
// 512 threads, block 128x128, warp 32x32 (4x4), KC=32, ping-pong smem.
// Buffer (base = 1024 + buf*20480):  A16@0  Wh@10240
//   each: 128 rows x 32 fp16, rows padded to 40 halves (80B).
#define GSM_TOTAL (1024 + 2 * 20480)
#define AS 40

template <int N, int DSTSEL, int SRCSEL>
__global__ __launch_bounds__(512, 1)
void gemm_tc(const float* __restrict__ Ap, const float* __restrict__ bias,
             float* __restrict__ Cp, float scale) {
    extern __shared__ __align__(1024) char smem[];
    const uint32_t sb = smem_u32(smem);

    const float* A = (SRCSEL == 0) ? Ap : g_O;
    float* C = (DSTSEL == 0) ? g_Q : ((DSTSEL == 1) ? g_KV : Cp);

    const int tid  = threadIdx.x;
    const int wid  = tid >> 5, lane = tid & 31;
    const int g    = lane >> 2, tig = lane & 3;
    const int wm   = wid & 3, wn = wid >> 2;
    const int n0   = blockIdx.x * 128;
    const long long m0 = (long long)blockIdx.y * 128;

    float* sBias = (float*)smem;
    if (tid < 128) sBias[tid] = bias[n0 + tid];

    float acc[2][4][4];
#pragma unroll
    for (int i = 0; i < 2; ++i)
#pragma unroll
        for (int j = 0; j < 4; ++j)
#pragma unroll
            for (int q = 0; q < 4; ++q) acc[i][j][q] = 0.f;

    auto loadA_regs = [&](int kc, float4* r) {
#pragma unroll
        for (int i = 0; i < 2; ++i) {
            int idx = tid + i * 512;
            int row = idx >> 3;
            int q = idx & 7;
            r[i] = *reinterpret_cast<const float4*>(
                A + (m0 + row) * 256 + kc * 32 + q * 4);
        }
    };
    auto stsA = [&](int buf, const float4* r) {
        char* base = smem + 1024 + buf * 20480;
#pragma unroll
        for (int i = 0; i < 2; ++i) {
            int idx = tid + i * 512;
            int row = idx >> 3;
            int q = idx & 7;
            float4 v = r[i];
            __half2 p0 = __floats2half2_rn(v.x, v.y);
            __half2 p1 = __floats2half2_rn(v.z, v.w);
            *reinterpret_cast<uint2*>(base + row * 80 + q * 8) =
                make_uint2(*reinterpret_cast<uint32_t*>(&p0),
                           *reinterpret_cast<uint32_t*>(&p1));
        }
    };
    auto cpB = [&](int kc, int buf) {
        uint32_t base = sb + 1024 + buf * 20480;
        int row = tid >> 2, seg = tid & 3;
        const __half* sh = g_Wh + (long long)(n0 + row) * 256 + kc * 32 + seg * 8;
        CP_ASYNC16(base + 10240 + row * 80 + seg * 16, sh);
    };
    auto mma_buf = [&](int buf) {
        const __half* Aw = (const __half*)(smem + 1024 + buf * 20480);
        const __half* Bh = Aw + 5120;
#pragma unroll
        for (int ks = 0; ks < 2; ++ks) {
            const int k0 = ks * 16;
            uint32_t af[2][4], bh[4][2];
#pragma unroll
            for (int mf = 0; mf < 2; ++mf) {
                const __half* p = Aw + (wm * 32 + mf * 16 + g) * AS + k0 + tig * 2;
                af[mf][0] = *(const uint32_t*)p;
                af[mf][1] = *(const uint32_t*)(p + 8 * AS);
                af[mf][2] = *(const uint32_t*)(p + 8);
                af[mf][3] = *(const uint32_t*)(p + 8 * AS + 8);
            }
#pragma unroll
            for (int nf = 0; nf < 4; ++nf) {
                const __half* p = Bh + (wn * 32 + nf * 8 + g) * AS + k0 + tig * 2;
                bh[nf][0] = *(const uint32_t*)p;
                bh[nf][1] = *(const uint32_t*)(p + 8);
            }
#pragma unroll
            for (int mf = 0; mf < 2; ++mf)
#pragma unroll
                for (int nf = 0; nf < 4; ++nf)
                    mma16816f16(acc[mf][nf], af[mf], bh[nf]);
        }
    };

    {
        float4 r[2];
        loadA_regs(0, r);
        cpB(0, 0);
        CP_COMMIT();
        stsA(0, r);
        CP_WAIT0();
        __syncthreads();
    }
#pragma unroll 1
    for (int kc = 0; kc < 8; ++kc) {
        const int buf = kc & 1;
        float4 r[2];
        if (kc < 7) {
            cpB(kc + 1, buf ^ 1);
            CP_COMMIT();
            loadA_regs(kc + 1, r);
        }
        mma_buf(buf);
        if (kc < 7) {
            stsA(buf ^ 1, r);
            CP_WAIT0();
            __syncthreads();
        }
    }

#pragma unroll
    for (int mf = 0; mf < 2; ++mf) {
#pragma unroll
        for (int nf = 0; nf < 4; ++nf) {
            const int cn = wn * 32 + nf * 8 + tig * 2;
            const float b0 = sBias[cn], b1 = sBias[cn + 1];
            const long long r0 = m0 + wm * 32 + mf * 16 + g;
            float* p0 = C + r0 * N + n0 + cn;
            float* p1 = C + (r0 + 8) * N + n0 + cn;
            *reinterpret_cast<float2*>(p0) =
                make_float2(scale * (acc[mf][nf][0] + b0), scale * (acc[mf][nf][1] + b1));
            *reinterpret_cast<float2*>(p1) =
                make_float2(scale * (acc[mf][nf][2] + b0), scale * (acc[mf][nf][3] + b1));
        }
    }
}

// ---- attention via fp16 HMMA: block = 1 window (R8, unchanged) ----------------
#define ASM_TOTAL (40960 + 36864)

__global__ __launch_bounds__(512, 1)
void attn_mma() {
    extern __shared__ __align__(16) char smem[];
    __half* sK  = (__half*)smem;                 // [h][key][40]
    __half* sVt = (__half*)(smem + 40960);       // [h][d][72]

    const int w = blockIdx.x;
    const int tid = threadIdx.x;
    const float* kvb = g_KV + (long long)w * 32768;

#pragma unroll
    for (int i = 0; i < 8; ++i) {
        int idx = tid + i * 512;
        int h   = idx >> 9;
        int rem = idx & 511;
        int key = rem >> 3;
        int dq  = (rem & 7) << 2;
        const float* kp = kvb + key * 512 + h * 32 + dq;
        float4 k4 = *reinterpret_cast<const float4*>(kp);
        __half2 k01 = __floats2half2_rn(k4.x, k4.y);
        __half2 k23 = __floats2half2_rn(k4.z, k4.w);
        *reinterpret_cast<uint2*>(sK + h * 2560 + key * 40 + dq) =
            make_uint2(*reinterpret_cast<uint32_t*>(&k01),
                       *reinterpret_cast<uint32_t*>(&k23));
        float4 v4 = *reinterpret_cast<const float4*>(kp + 256);
        __half* vt = sVt + h * 2304 + key;
        vt[(dq + 0) * 72] = __float2half_rn(v4.x);
        vt[(dq + 1) * 72] = __float2half_rn(v4.y);
        vt[(dq + 2) * 72] = __float2half_rn(v4.z);
        vt[(dq + 3) * 72] = __float2half_rn(v4.w);
    }
    __syncthreads();

    const int wid = tid >> 5, lane = tid & 31;
    const int g = lane >> 2, t = lane & 3;
    const int h = wid >> 1, mh = wid & 1;
    const __half* Kh = sK + h * 2560;
    const __half* Vh = sVt + h * 2304;

    uint32_t qf[2][2][4];
    const float* qbase = g_Q + (long long)w * 16384 + h * 32;
#pragma unroll
    for (int mt = 0; mt < 2; ++mt) {
        const int R = (mh * 2 + mt) * 16 + g;
#pragma unroll
        for (int kb = 0; kb < 2; ++kb) {
            const int c = kb * 16 + t * 2;
            float2 v0 = *reinterpret_cast<const float2*>(qbase + R * 256 + c);
            float2 v1 = *reinterpret_cast<const float2*>(qbase + (R + 8) * 256 + c);
            float2 v2 = *reinterpret_cast<const float2*>(qbase + R * 256 + c + 8);
            float2 v3 = *reinterpret_cast<const float2*>(qbase + (R + 8) * 256 + c + 8);
            qf[mt][kb][0] = h2pack(v0.x, v0.y);
            qf[mt][kb][1] = h2pack(v1.x, v1.y);
            qf[mt][kb][2] = h2pack(v2.x, v2.y);
            qf[mt][kb][3] = h2pack(v3.x, v3.y);
        }
    }

    float S[2][8][4];
#pragma unroll
    for (int mt = 0; mt < 2; ++mt)
#pragma unroll
        for (int nb = 0; nb < 8; ++nb)
#pragma unroll
            for (int q = 0; q < 4; ++q) S[mt][nb][q] = 0.f;

#pragma unroll
    for (int nb = 0; nb < 8; ++nb) {
        uint32_t bf[2][2];
#pragma unroll
        for (int kb = 0; kb < 2; ++kb) {
            const __half* p = Kh + (8 * nb + g) * 40 + kb * 16 + t * 2;
            bf[kb][0] = *(const uint32_t*)p;
            bf[kb][1] = *(const uint32_t*)(p + 8);
        }
#pragma unroll
        for (int mt = 0; mt < 2; ++mt)
#pragma unroll
            for (int kb = 0; kb < 2; ++kb)
                mma16816f16(S[mt][nb], qf[mt][kb], bf[kb]);
    }

    const float* bb = g_bias + h * 4096;
#pragma unroll
    for (int mt = 0; mt < 2; ++mt) {
        const int R = (mh * 2 + mt) * 16 + g;
#pragma unroll
        for (int nb = 0; nb < 8; ++nb) {
            const int c = nb * 8 + t * 2;
            float2 b0 = *reinterpret_cast<const float2*>(bb + R * 64 + c);
            float2 b1 = *reinterpret_cast<const float2*>(bb + (R + 8) * 64 + c);
            S[mt][nb][0] += b0.x; S[mt][nb][1] += b0.y;
            S[mt][nb][2] += b1.x; S[mt][nb][3] += b1.y;
        }
    }

    float inv[2][2];
#pragma unroll
    for (int mt = 0; mt < 2; ++mt) {
        float m0 = -1e30f, m1 = -1e30f;
#pragma unroll
        for (int nb = 0; nb < 8; ++nb) {
            m0 = fmaxf(m0, fmaxf(S[mt][nb][0], S[mt][nb][1]));
            m1 = fmaxf(m1, fmaxf(S[mt][nb][2], S[mt][nb][3]));
        }
        m0 = fmaxf(m0, __shfl_xor_sync(0xFFFFFFFF, m0, 1));
        m0 = fmaxf(m0, __shfl_xor_sync(0xFFFFFFFF, m0, 2));
        m1 = fmaxf(m1, __shfl_xor_sync(0xFFFFFFFF, m1, 1));
        m1 = fmaxf(m1, __shfl_xor_sync(0xFFFFFFFF, m1, 2));
        float s0 = 0.f, s1 = 0.f;
#pragma unroll
        for (int nb = 0; nb < 8; ++nb) {
            S[mt][nb][0] = __expf(S[mt][nb][0] - m0);
            S[mt][nb][1] = __expf(S[mt][nb][1] - m0);
            S[mt][nb][2] = __expf(S[mt][nb][2] - m1);
            S[mt][nb][3] = __expf(S[mt][nb][3] - m1);
            s0 += S[mt][nb][0] + S[mt][nb][1];
            s1 += S[mt][nb][2] + S[mt][nb][3];
        }
        s0 += __shfl_xor_sync(0xFFFFFFFF, s0, 1);
        s0 += __shfl_xor_sync(0xFFFFFFFF, s0, 2);
        s1 += __shfl_xor_sync(0xFFFFFFFF, s1, 1);
        s1 += __shfl_xor_sync(0xFFFFFFFF, s1, 2);
        inv[mt][0] = 1.f / s0;
        inv[mt][1] = 1.f / s1;
    }

    uint32_t pf[2][4][4];
#pragma unroll
    for (int mt = 0; mt < 2; ++mt)
#pragma unroll
        for (int kb = 0; kb < 4; ++kb) {
            pf[mt][kb][0] = h2pack(S[mt][2 * kb][0],     S[mt][2 * kb][1]);
            pf[mt][kb][1] = h2pack(S[mt][2 * kb][2],     S[mt][2 * kb][3]);
            pf[mt][kb][2] = h2pack(S[mt][2 * kb + 1][0], S[mt][2 * kb + 1][1]);
            pf[mt][kb][3] = h2pack(S[mt][2 * kb + 1][2], S[mt][2 * kb + 1][3]);
        }

    float O[2][4][4];
#pragma unroll
    for (int mt = 0; mt < 2; ++mt)
#pragma unroll
        for (int nb = 0; nb < 4; ++nb)
#pragma unroll
            for (int q = 0; q < 4; ++q) O[mt][nb][q] = 0.f;

#pragma unroll
    for (int nb = 0; nb < 4; ++nb) {
        uint32_t vf[4][2];
#pragma unroll
        for (int kb = 0; kb < 4; ++kb) {
            const __half* p = Vh + (8 * nb + g) * 72 + kb * 16 + t * 2;
            vf[kb][0] = *(const uint32_t*)p;
            vf[kb][1] = *(const uint32_t*)(p + 8);
        }
#pragma unroll
        for (int mt = 0; mt < 2; ++mt)
#pragma unroll
            for (int kb = 0; kb < 4; ++kb)
                mma16816f16(O[mt][nb], pf[mt][kb], vf[kb]);
    }

    float* ob = g_O + (long long)w * 16384 + h * 32;
#pragma unroll
    for (int mt = 0; mt < 2; ++mt) {
        const int R = (mh * 2 + mt) * 16 + g;
#pragma unroll
        for (int nb = 0; nb < 4; ++nb) {
            const int c = nb * 8 + t * 2;
            *reinterpret_cast<float2*>(ob + R * 256 + c) =
                make_float2(O[mt][nb][0] * inv[mt][0], O[mt][nb][1] * inv[mt][0]);
            *reinterpret_cast<float2*>(ob + (R + 8) * 256 + c) =
                make_float2(O[mt][nb][2] * inv[mt][1], O[mt][nb][3] * inv[mt][1]);
        }
    }
}

// ---------------------------------------------------------------------------
extern "C" void kernel_launch(void* const* d_in, const int* in_sizes, int n_in,
                              void* d_out, int out_size) {
    const float* xq  = (const float*)d_in[0];
    const float* xs  = (const float*)d_in[1];
    const float* Wq  = (const float*)d_in[2];
    const float* bq  = (const float*)d_in[3];
    const float* Wkv = (const float*)d_in[4];
    const float* bkv = (const float*)d_in[5];
    const float* bt  = (const float*)d_in[6];
    const float* Wp  = (const float*)d_in[7];
    const float* bp  = (const float*)d_in[8];
    float* out = (float*)d_out;

    const int M = in_sizes[0] / 256;            // 262144
    const int B = M / 64;                       // 4096
    const float scale = 0.17677669529663687f;   // 32^-0.5

    cudaFuncSetAttribute(gemm_tc<256, 0, 0>,
                         cudaFuncAttributeMaxDynamicSharedMemorySize, GSM_TOTAL);
    cudaFuncSetAttribute(gemm_tc<512, 1, 0>,
                         cudaFuncAttributeMaxDynamicSharedMemorySize, GSM_TOTAL);
    cudaFuncSetAttribute(gemm_tc<256, 2, 1>,
                         cudaFuncAttributeMaxDynamicSharedMemorySize, GSM_TOTAL);
    cudaFuncSetAttribute(attn_mma,
                         cudaFuncAttributeMaxDynamicSharedMemorySize, ASM_TOTAL);

    bias_kernel<<<128, 256>>>(bt);

    convw_kernel<<<256, 256>>>(Wq, 256);
    gemm_tc<256, 0, 0><<<dim3(2, M / 128), 512, GSM_TOTAL>>>(xq, bq, nullptr, scale);

    convw_kernel<<<512, 256>>>(Wkv, 512);
    gemm_tc<512, 1, 0><<<dim3(4, M / 128), 512, GSM_TOTAL>>>(xs, bkv, nullptr, 1.f);

    attn_mma<<<B, 512, ASM_TOTAL>>>();

    convw_kernel<<<256, 256>>>(Wp, 256);
    gemm_tc<256, 2, 1><<<dim3(2, M / 128), 512, GSM_TOTAL>>>(nullptr, bp, out, 1.f);
}

// round 10
// speedup vs baseline: 2.3292x; 1.0871x over previous
#include <cuda_runtime.h>
#include <cuda_fp16.h>
#include <cstdint>

// ---------------------------------------------------------------------------
// WindowedCrossAttention — R10
//   fp16 intermediates (g_Q/g_KV/g_O) — zero added rounding (consumers already
//   rounded them), half the intermediate DRAM traffic, no consumer cvt chains.
//   GEMM: single-pass fp16 HMMA + ldmatrix.x4 fragment loads; out-GEMM A via
//   direct cp.async. Attention: R8 structure with fp16 I/O.
// ---------------------------------------------------------------------------

__device__ __half g_Q [4096ull * 64ull * 256ull];
__device__ __half g_KV[4096ull * 64ull * 512ull];
__device__ __half g_O [4096ull * 64ull * 256ull];
__device__ float  g_bias[8 * 64 * 64];                // [h][q][k]
__device__ __half g_Wh[512 * 256];                    // fp16(W), [n][k]

// ---- helpers ----------------------------------------------------------------
__device__ __forceinline__ uint32_t smem_u32(const void* p) {
    uint32_t a;
    asm("{ .reg .u64 t; cvta.to.shared.u64 t, %1; cvt.u32.u64 %0, t; }" : "=r"(a) : "l"(p));
    return a;
}
__device__ __forceinline__ void mma16816f16(float* c, const uint32_t* a, const uint32_t* b) {
    asm volatile(
        "mma.sync.aligned.m16n8k16.row.col.f32.f16.f16.f32 "
        "{%0,%1,%2,%3}, {%4,%5,%6,%7}, {%8,%9}, {%0,%1,%2,%3};"
        : "+f"(c[0]), "+f"(c[1]), "+f"(c[2]), "+f"(c[3])
        : "r"(a[0]), "r"(a[1]), "r"(a[2]), "r"(a[3]), "r"(b[0]), "r"(b[1]));
}
__device__ __forceinline__ void ldm_x4(uint32_t* r, uint32_t addr) {
    asm volatile("ldmatrix.sync.aligned.m8n8.x4.shared.b16 {%0,%1,%2,%3}, [%4];"
                 : "=r"(r[0]), "=r"(r[1]), "=r"(r[2]), "=r"(r[3]) : "r"(addr));
}
__device__ __forceinline__ uint32_t h2pack(float a, float b) {
    __half2 h = __floats2half2_rn(a, b);
    return *reinterpret_cast<uint32_t*>(&h);
}
#define CP_ASYNC16(dst, src) \
    asm volatile("cp.async.cg.shared.global [%0], [%1], 16;" :: "r"(dst), "l"(src))
#define CP_COMMIT() asm volatile("cp.async.commit_group;")
#define CP_WAIT0()  asm volatile("cp.async.wait_group 0;")

// ---- relative-position bias: g_bias[h][q][k] = bt[rel(q,k)][h] ---------------
__global__ void bias_kernel(const float* __restrict__ bt) {
    int idx = blockIdx.x * 256 + threadIdx.x;
    if (idx >= 8 * 64 * 64) return;
    int h  = idx >> 12;
    int nm = idx & 4095;
    int q = nm >> 6, k = nm & 63;
    int dy = (q >> 3) - (k >> 3);
    int dx = (q & 7) - (k & 7);
    int r  = (dy + 7) * 15 + (dx + 7);
    g_bias[idx] = bt[r * 8 + h];
}

// ---- W -> fp16, transposed [n][k] --------------------------------------------
__global__ void convw_kernel(const float* __restrict__ W, int Ncols) {
    int idx = blockIdx.x * 256 + threadIdx.x;
    if (idx >= Ncols * 256) return;
    int n = idx >> 8;
    int k = idx & 255;
    g_Wh[idx] = __float2half_rn(W[k * Ncols + n]);
}

// ---- single-pass fp16 GEMM:  C[M,N] = scale*(A[M,256] @ W + bias) -------------
// 512 threads, block 128x128, warp 32x32 (4x4), KC=32, ping-pong smem.
// Buffer (base = 1024 + buf*20480):  A16@0  Wh@10240  (rows padded to 40 halves)
// SRCSEL: 0 -> fp32 A param (cvt in loader), 1 -> g_O fp16 (direct cp.async)
// DSTSEL: 0 -> g_Q fp16, 1 -> g_KV fp16, 2 -> fp32 C param
#define GSM_TOTAL (1024 + 2 * 20480)

template <int N, int DSTSEL, int SRCSEL>
__global__ __launch_bounds__(512, 1)
void gemm_tc(const float* __restrict__ Ap, const float* __restrict__ bias,
             float* __restrict__ Cp, float scale) {
    extern __shared__ __align__(1024) char smem[];
    const uint32_t sb = smem_u32(smem);

    const int tid  = threadIdx.x;
    const int wid  = tid >> 5, lane = tid & 31;
    const int g    = lane >> 2, tig = lane & 3;
    const int wm   = wid & 3, wn = wid >> 2;
    const int n0   = blockIdx.x * 128;
    const long long m0 = (long long)blockIdx.y * 128;

    float* sBias = (float*)smem;
    if (tid < 128) sBias[tid] = bias[n0 + tid];

    float acc[2][4][4];
#pragma unroll
    for (int i = 0; i < 2; ++i)
#pragma unroll
        for (int j = 0; j < 4; ++j)
#pragma unroll
            for (int q = 0; q < 4; ++q) acc[i][j][q] = 0.f;

    // ldmatrix per-lane base addresses (byte offsets within a buffer)
    const uint32_t lrow = lane & 15, lcol = (lane >> 4) * 8;
    const uint32_t aOff = (wm * 32 + lrow) * 80 + lcol * 2;          // A tile
    const uint32_t bOff = 10240 + (wn * 32 + lrow) * 80 + lcol * 2;  // B tile

    auto loadA_regs = [&](int kc, float4* r) {
#pragma unroll
        for (int i = 0; i < 2; ++i) {
            int idx = tid + i * 512;
            int row = idx >> 3;
            int q = idx & 7;
            r[i] = *reinterpret_cast<const float4*>(
                Ap + (m0 + row) * 256 + kc * 32 + q * 4);
        }
    };
    auto stsA = [&](int buf, const float4* r) {
        char* base = smem + 1024 + buf * 20480;
#pragma unroll
        for (int i = 0; i < 2; ++i) {
            int idx = tid + i * 512;
            int row = idx >> 3;
            int q = idx & 7;
            float4 v = r[i];
            __half2 p0 = __floats2half2_rn(v.x, v.y);
            __half2 p1 = __floats2half2_rn(v.z, v.w);
            *reinterpret_cast<uint2*>(base + row * 80 + q * 8) =
                make_uint2(*reinterpret_cast<uint32_t*>(&p0),
                           *reinterpret_cast<uint32_t*>(&p1));
        }
    };
    auto cpA16 = [&](int kc, int buf) {           // SRCSEL==1: A = g_O fp16
        uint32_t base = sb + 1024 + buf * 20480;
        int row = tid >> 2, seg = tid & 3;
        const __half* src = g_O + (m0 + row) * 256 + kc * 32 + seg * 8;
        CP_ASYNC16(base + row * 80 + seg * 16, src);
    };
    auto cpB = [&](int kc, int buf) {
        uint32_t base = sb + 1024 + buf * 20480;
        int row = tid >> 2, seg = tid & 3;
        const __half* sh = g_Wh + (long long)(n0 + row) * 256 + kc * 32 + seg * 8;
        CP_ASYNC16(base + 10240 + row * 80 + seg * 16, sh);
    };
    auto mma_buf = [&](int buf) {
        const uint32_t bufb = sb + 1024 + buf * 20480;
#pragma unroll
        for (int ks = 0; ks < 2; ++ks) {
            uint32_t af[2][4], bm[2][4];
#pragma unroll
            for (int mf = 0; mf < 2; ++mf)
                ldm_x4(af[mf], bufb + aOff + mf * 16 * 80 + ks * 32);
#pragma unroll
            for (int p = 0; p < 2; ++p)
                ldm_x4(bm[p], bufb + bOff + p * 16 * 80 + ks * 32);
            // bm[p] = {bh[2p][0], bh[2p+1][0], bh[2p][1], bh[2p+1][1]}
#pragma unroll
            for (int mf = 0; mf < 2; ++mf)
#pragma unroll
                for (int p = 0; p < 2; ++p) {
                    uint32_t b0[2] = {bm[p][0], bm[p][2]};
                    uint32_t b1[2] = {bm[p][1], bm[p][3]};
                    mma16816f16(acc[mf][2 * p + 0], af[mf], b0);
                    mma16816f16(acc[mf][2 * p + 1], af[mf], b1);
                }
        }
    };

    // ---- prologue ----
    if (SRCSEL == 1) {
        cpA16(0, 0);
        cpB(0, 0);
        CP_COMMIT();
        CP_WAIT0();
        __syncthreads();
    } else {
        float4 r[2];
        loadA_regs(0, r);
        cpB(0, 0);
        CP_COMMIT();
        stsA(0, r);
        CP_WAIT0();
        __syncthreads();
    }
    // ---- main loop: 8 k-chunks ----
#pragma unroll 1
    for (int kc = 0; kc < 8; ++kc) {
        const int buf = kc & 1;
        float4 r[2];
        if (kc < 7) {
            if (SRCSEL == 1) {
                cpA16(kc + 1, buf ^ 1);
                cpB(kc + 1, buf ^ 1);
                CP_COMMIT();
            } else {
                cpB(kc + 1, buf ^ 1);
                CP_COMMIT();
                loadA_regs(kc + 1, r);
            }
        }
        mma_buf(buf);
        if (kc < 7) {
            if (SRCSEL == 0) stsA(buf ^ 1, r);
            CP_WAIT0();
            __syncthreads();
        }
    }

    // ---- epilogue ----
#pragma unroll
    for (int mf = 0; mf < 2; ++mf) {
#pragma unroll
        for (int nf = 0; nf < 4; ++nf) {
            const int cn = wn * 32 + nf * 8 + tig * 2;
            const float b0 = sBias[cn], b1 = sBias[cn + 1];
            const long long r0 = m0 + wm * 32 + mf * 16 + g;
            float v0 = scale * (acc[mf][nf][0] + b0);
            float v1 = scale * (acc[mf][nf][1] + b1);
            float v2 = scale * (acc[mf][nf][2] + b0);
            float v3 = scale * (acc[mf][nf][3] + b1);
            if (DSTSEL == 2) {
                float* p0 = Cp + r0 * N + n0 + cn;
                float* p1 = Cp + (r0 + 8) * N + n0 + cn;
                *reinterpret_cast<float2*>(p0) = make_float2(v0, v1);
                *reinterpret_cast<float2*>(p1) = make_float2(v2, v3);
            } else {
                __half* C16 = (DSTSEL == 0) ? g_Q : g_KV;
                *reinterpret_cast<uint32_t*>(C16 + r0 * N + n0 + cn) = h2pack(v0, v1);
                *reinterpret_cast<uint32_t*>(C16 + (r0 + 8) * N + n0 + cn) = h2pack(v2, v3);
            }
        }
    }
}

// ---- attention via fp16 HMMA: block = 1 window --------------------------------
// smem: sK [8][64][40] halves (40960 B) + sVt [8][32][72] halves (36864 B)
#define ASM_TOTAL (40960 + 36864)

__global__ __launch_bounds__(512, 1)
void attn_mma() {
    extern __shared__ __align__(16) char smem[];
    __half* sK  = (__half*)smem;                 // [h][key][40]
    __half* sVt = (__half*)(smem + 40960);       // [h][d][72]

    const int w = blockIdx.x;
    const int tid = threadIdx.x;
    const __half* kvb = g_KV + (long long)w * 32768;

    // stage K (raw uint4 copies) and V (transpose scatter); 2048 uint4 each
#pragma unroll
    for (int i = 0; i < 4; ++i) {
        int idx = tid + i * 512;                 // 0..2047
        int h   = idx >> 8;
        int rem = idx & 255;
        int key = rem >> 2;
        int d8  = (rem & 3) * 8;
        const __half* src = kvb + key * 512 + h * 32 + d8;
        *reinterpret_cast<uint4*>(sK + h * 2560 + key * 40 + d8) =
            *reinterpret_cast<const uint4*>(src);
        uint4 v4 = *reinterpret_cast<const uint4*>(src + 256);
        const __half* vh = reinterpret_cast<const __half*>(&v4);
        __half* vt = sVt + h * 2304 + key;
#pragma unroll
        for (int j = 0; j < 8; ++j) vt[(d8 + j) * 72] = vh[j];
    }
    __syncthreads();

    const int wid = tid >> 5, lane = tid & 31;
    const int g = lane >> 2, t = lane & 3;
    const int h = wid >> 1, mh = wid & 1;
    const __half* Kh = sK + h * 2560;
    const __half* Vh = sVt + h * 2304;

    // Q fragments: direct LDG.32 of fp16 pairs
    uint32_t qf[2][2][4];
    const __half* qbase = g_Q + (long long)w * 16384 + h * 32;
#pragma unroll
    for (int mt = 0; mt < 2; ++mt) {
        const int R = (mh * 2 + mt) * 16 + g;
#pragma unroll
        for (int kb = 0; kb < 2; ++kb) {
            const int c = kb * 16 + t * 2;
            qf[mt][kb][0] = *reinterpret_cast<const uint32_t*>(qbase + R * 256 + c);
            qf[mt][kb][1] = *reinterpret_cast<const uint32_t*>(qbase + (R + 8) * 256 + c);
            qf[mt][kb][2] = *reinterpret_cast<const uint32_t*>(qbase + R * 256 + c + 8);
            qf[mt][kb][3] = *reinterpret_cast<const uint32_t*>(qbase + (R + 8) * 256 + c + 8);
        }
    }

    float S[2][8][4];
#pragma unroll
    for (int mt = 0; mt < 2; ++mt)
#pragma unroll
        for (int nb = 0; nb < 8; ++nb)
#pragma unroll
            for (int q = 0; q < 4; ++q) S[mt][nb][q] = 0.f;

#pragma unroll
    for (int nb = 0; nb < 8; ++nb) {
        uint32_t bf[2][2];
#pragma unroll
        for (int kb = 0; kb < 2; ++kb) {
            const __half* p = Kh + (8 * nb + g) * 40 + kb * 16 + t * 2;
            bf[kb][0] = *(const uint32_t*)p;
            bf[kb][1] = *(const uint32_t*)(p + 8);
        }
#pragma unroll
        for (int mt = 0; mt < 2; ++mt)
#pragma unroll
            for (int kb = 0; kb < 2; ++kb)
                mma16816f16(S[mt][nb], qf[mt][kb], bf[kb]);
    }

    const float* bb = g_bias + h * 4096;
#pragma unroll
    for (int mt = 0; mt < 2; ++mt) {
        const int R = (mh * 2 + mt) * 16 + g;
#pragma unroll
        for (int nb = 0; nb < 8; ++nb) {
            const int c = nb * 8 + t * 2;
            float2 b0 = *reinterpret_cast<const float2*>(bb + R * 64 + c);
            float2 b1 = *reinterpret_cast<const float2*>(bb + (R + 8) * 64 + c);
            S[mt][nb][0] += b0.x; S[mt][nb][1] += b0.y;
            S[mt][nb][2] += b1.x; S[mt][nb][3] += b1.y;
        }
    }

    float inv[2][2];
#pragma unroll
    for (int mt = 0; mt < 2; ++mt) {
        float m0 = -1e30f, m1 = -1e30f;
#pragma unroll
        for (int nb = 0; nb < 8; ++nb) {
            m0 = fmaxf(m0, fmaxf(S[mt][nb][0], S[mt][nb][1]));
            m1 = fmaxf(m1, fmaxf(S[mt][nb][2], S[mt][nb][3]));
        }
        m0 = fmaxf(m0, __shfl_xor_sync(0xFFFFFFFF, m0, 1));
        m0 = fmaxf(m0, __shfl_xor_sync(0xFFFFFFFF, m0, 2));
        m1 = fmaxf(m1, __shfl_xor_sync(0xFFFFFFFF, m1, 1));
        m1 = fmaxf(m1, __shfl_xor_sync(0xFFFFFFFF, m1, 2));
        float s0 = 0.f, s1 = 0.f;
#pragma unroll
        for (int nb = 0; nb < 8; ++nb) {
            S[mt][nb][0] = __expf(S[mt][nb][0] - m0);
            S[mt][nb][1] = __expf(S[mt][nb][1] - m0);
            S[mt][nb][2] = __expf(S[mt][nb][2] - m1);
            S[mt][nb][3] = __expf(S[mt][nb][3] - m1);
            s0 += S[mt][nb][0] + S[mt][nb][1];
            s1 += S[mt][nb][2] + S[mt][nb][3];
        }
        s0 += __shfl_xor_sync(0xFFFFFFFF, s0, 1);
        s0 += __shfl_xor_sync(0xFFFFFFFF, s0, 2);
        s1 += __shfl_xor_sync(0xFFFFFFFF, s1, 1);
        s1 += __shfl_xor_sync(0xFFFFFFFF, s1, 2);
        inv[mt][0] = 1.f / s0;
        inv[mt][1] = 1.f / s1;
    }

    uint32_t pf[2][4][4];
#pragma unroll
    for (int mt = 0; mt < 2; ++mt)
#pragma unroll
        for (int kb = 0; kb < 4; ++kb) {
            pf[mt][kb][0] = h2pack(S[mt][2 * kb][0],     S[mt][2 * kb][1]);
            pf[mt][kb][1] = h2pack(S[mt][2 * kb][2],     S[mt][2 * kb][3]);
            pf[mt][kb][2] = h2pack(S[mt][2 * kb + 1][0], S[mt][2 * kb + 1][1]);
            pf[mt][kb][3] = h2pack(S[mt][2 * kb + 1][2], S[mt][2 * kb + 1][3]);
        }

    float O[2][4][4];
#pragma unroll
    for (int mt = 0; mt < 2; ++mt)
#pragma unroll
        for (int nb = 0; nb < 4; ++nb)
#pragma unroll
            for (int q = 0; q < 4; ++q) O[mt][nb][q] = 0.f;

#pragma unroll
    for (int nb = 0; nb < 4; ++nb) {
        uint32_t vf[4][2];
#pragma unroll
        for (int kb = 0; kb < 4; ++kb) {
            const __half* p = Vh + (8 * nb + g) * 72 + kb * 16 + t * 2;
            vf[kb][0] = *(const uint32_t*)p;
            vf[kb][1] = *(const uint32_t*)(p + 8);
        }
#pragma unroll
        for (int mt = 0; mt < 2; ++mt)
#pragma unroll
            for (int kb = 0; kb < 4; ++kb)
                mma16816f16(O[mt][nb], pf[mt][kb], vf[kb]);
    }

    __half* ob = g_O + (long long)w * 16384 + h * 32;
#pragma unroll
    for (int mt = 0; mt < 2; ++mt) {
        const int R = (mh * 2 + mt) * 16 + g;
#pragma unroll
        for (int nb = 0; nb < 4; ++nb) {
            const int c = nb * 8 + t * 2;
            *reinterpret_cast<uint32_t*>(ob + R * 256 + c) =
                h2pack(O[mt][nb][0] * inv[mt][0], O[mt][nb][1] * inv[mt][0]);
            *reinterpret_cast<uint32_t*>(ob + (R + 8) * 256 + c) =
                h2pack(O[mt][nb][2] * inv[mt][1], O[mt][nb][3] * inv[mt][1]);
        }
    }
}

// ---------------------------------------------------------------------------
extern "C" void kernel_launch(void* const* d_in, const int* in_sizes, int n_in,
                              void* d_out, int out_size) {
    const float* xq  = (const float*)d_in[0];
    const float* xs  = (const float*)d_in[1];
    const float* Wq  = (const float*)d_in[2];
    const float* bq  = (const float*)d_in[3];
    const float* Wkv = (const float*)d_in[4];
    const float* bkv = (const float*)d_in[5];
    const float* bt  = (const float*)d_in[6];
    const float* Wp  = (const float*)d_in[7];
    const float* bp  = (const float*)d_in[8];
    float* out = (float*)d_out;

    const int M = in_sizes[0] / 256;            // 262144
    const int B = M / 64;                       // 4096
    const float scale = 0.17677669529663687f;   // 32^-0.5

    cudaFuncSetAttribute(gemm_tc<256, 0, 0>,
                         cudaFuncAttributeMaxDynamicSharedMemorySize, GSM_TOTAL);
    cudaFuncSetAttribute(gemm_tc<512, 1, 0>,
                         cudaFuncAttributeMaxDynamicSharedMemorySize, GSM_TOTAL);
    cudaFuncSetAttribute(gemm_tc<256, 2, 1>,
                         cudaFuncAttributeMaxDynamicSharedMemorySize, GSM_TOTAL);
    cudaFuncSetAttribute(attn_mma,
                         cudaFuncAttributeMaxDynamicSharedMemorySize, ASM_TOTAL);

    bias_kernel<<<128, 256>>>(bt);

    convw_kernel<<<256, 256>>>(Wq, 256);
    gemm_tc<256, 0, 0><<<dim3(2, M / 128), 512, GSM_TOTAL>>>(xq, bq, nullptr, scale);

    convw_kernel<<<512, 256>>>(Wkv, 512);
    gemm_tc<512, 1, 0><<<dim3(4, M / 128), 512, GSM_TOTAL>>>(xs, bkv, nullptr, 1.f);

    attn_mma<<<B, 512, ASM_TOTAL>>>();

    convw_kernel<<<256, 256>>>(Wp, 256);
    gemm_tc<256, 2, 1><<<dim3(2, M / 128), 512, GSM_TOTAL>>>(nullptr, bp, out, 1.f);
}

// round 11
// speedup vs baseline: 2.9321x; 1.2589x over previous
#include <cuda_runtime.h>
#include <cuda_fp16.h>
#include <cstdint>

// ---------------------------------------------------------------------------
// WindowedCrossAttention — R11
//   GEMM: 256-thread blocks (8 warps, warp tile 64x32), __launch_bounds__(256,2)
//   -> 2 independent blocks/SM: barrier/latency stalls of one block overlap
//   with HMMA issue of the other. Same 128x128 tile, smem layout, fp16 path.
//   Attention / bias / convw: R10 unchanged.
// ---------------------------------------------------------------------------

__device__ __half g_Q [4096ull * 64ull * 256ull];
__device__ __half g_KV[4096ull * 64ull * 512ull];
__device__ __half g_O [4096ull * 64ull * 256ull];
__device__ float  g_bias[8 * 64 * 64];                // [h][q][k]
__device__ __half g_Wh[512 * 256];                    // fp16(W), [n][k]

// ---- helpers ----------------------------------------------------------------
__device__ __forceinline__ uint32_t smem_u32(const void* p) {
    uint32_t a;
    asm("{ .reg .u64 t; cvta.to.shared.u64 t, %1; cvt.u32.u64 %0, t; }" : "=r"(a) : "l"(p));
    return a;
}
__device__ __forceinline__ void mma16816f16(float* c, const uint32_t* a, const uint32_t* b) {
    asm volatile(
        "mma.sync.aligned.m16n8k16.row.col.f32.f16.f16.f32 "
        "{%0,%1,%2,%3}, {%4,%5,%6,%7}, {%8,%9}, {%0,%1,%2,%3};"
        : "+f"(c[0]), "+f"(c[1]), "+f"(c[2]), "+f"(c[3])
        : "r"(a[0]), "r"(a[1]), "r"(a[2]), "r"(a[3]), "r"(b[0]), "r"(b[1]));
}
__device__ __forceinline__ void ldm_x4(uint32_t* r, uint32_t addr) {
    asm volatile("ldmatrix.sync.aligned.m8n8.x4.shared.b16 {%0,%1,%2,%3}, [%4];"
                 : "=r"(r[0]), "=r"(r[1]), "=r"(r[2]), "=r"(r[3]) : "r"(addr));
}
__device__ __forceinline__ uint32_t h2pack(float a, float b) {
    __half2 h = __floats2half2_rn(a, b);
    return *reinterpret_cast<uint32_t*>(&h);
}
#define CP_ASYNC16(dst, src) \
    asm volatile("cp.async.cg.shared.global [%0], [%1], 16;" :: "r"(dst), "l"(src))
#define CP_COMMIT() asm volatile("cp.async.commit_group;")
#define CP_WAIT0()  asm volatile("cp.async.wait_group 0;")

// ---- relative-position bias: g_bias[h][q][k] = bt[rel(q,k)][h] ---------------
__global__ void bias_kernel(const float* __restrict__ bt) {
    int idx = blockIdx.x * 256 + threadIdx.x;
    if (idx >= 8 * 64 * 64) return;
    int h  = idx >> 12;
    int nm = idx & 4095;
    int q = nm >> 6, k = nm & 63;
    int dy = (q >> 3) - (k >> 3);
    int dx = (q & 7) - (k & 7);
    int r  = (dy + 7) * 15 + (dx + 7);
    g_bias[idx] = bt[r * 8 + h];
}

// ---- W -> fp16, transposed [n][k] --------------------------------------------
__global__ void convw_kernel(const float* __restrict__ W, int Ncols) {
    int idx = blockIdx.x * 256 + threadIdx.x;
    if (idx >= Ncols * 256) return;
    int n = idx >> 8;
    int k = idx & 255;
    g_Wh[idx] = __float2half_rn(W[k * Ncols + n]);
}

// ---- single-pass fp16 GEMM:  C[M,N] = scale*(A[M,256] @ W + bias) -------------
// 256 threads, 8 warps (2m x 4n), warp tile 64x32, block tile 128x128, KC=32.
// Buffer (base = 1024 + buf*20480): A16@0  Wh@10240  (rows padded to 40 halves)
#define GSM_TOTAL (1024 + 2 * 20480)

template <int N, int DSTSEL, int SRCSEL>
__global__ __launch_bounds__(256, 2)
void gemm_tc(const float* __restrict__ Ap, const float* __restrict__ bias,
             float* __restrict__ Cp, float scale) {
    extern __shared__ __align__(1024) char smem[];
    const uint32_t sb = smem_u32(smem);

    const int tid  = threadIdx.x;
    const int wid  = tid >> 5, lane = tid & 31;
    const int g    = lane >> 2, tig = lane & 3;
    const int wm   = wid & 1, wn = wid >> 1;       // 2x4 warp grid
    const int n0   = blockIdx.x * 128;
    const long long m0 = (long long)blockIdx.y * 128;

    float* sBias = (float*)smem;
    if (tid < 128) sBias[tid] = bias[n0 + tid];

    float acc[4][4][4];                             // warp tile 64x32
#pragma unroll
    for (int i = 0; i < 4; ++i)
#pragma unroll
        for (int j = 0; j < 4; ++j)
#pragma unroll
            for (int q = 0; q < 4; ++q) acc[i][j][q] = 0.f;

    const uint32_t lrow = lane & 15, lcol = (lane >> 4) * 8;
    const uint32_t aOff = (wm * 64 + lrow) * 80 + lcol * 2;
    const uint32_t bOff = 10240 + (wn * 32 + lrow) * 80 + lcol * 2;

    auto loadA_regs = [&](int kc, float4* r) {
#pragma unroll
        for (int i = 0; i < 4; ++i) {
            int idx = tid + i * 256;                // 1024 float4
            int row = idx >> 3;
            int q = idx & 7;
            r[i] = *reinterpret_cast<const float4*>(
                Ap + (m0 + row) * 256 + kc * 32 + q * 4);
        }
    };
    auto stsA = [&](int buf, const float4* r) {
        char* base = smem + 1024 + buf * 20480;
#pragma unroll
        for (int i = 0; i < 4; ++i) {
            int idx = tid + i * 256;
            int row = idx >> 3;
            int q = idx & 7;
            float4 v = r[i];
            __half2 p0 = __floats2half2_rn(v.x, v.y);
            __half2 p1 = __floats2half2_rn(v.z, v.w);
            *reinterpret_cast<uint2*>(base + row * 80 + q * 8) =
                make_uint2(*reinterpret_cast<uint32_t*>(&p0),
                           *reinterpret_cast<uint32_t*>(&p1));
        }
    };
    auto cpA16 = [&](int kc, int buf) {             // SRCSEL==1: A = g_O fp16
        uint32_t base = sb + 1024 + buf * 20480;
#pragma unroll
        for (int i = 0; i < 2; ++i) {
            int idx = tid + i * 256;                // 512 lines of 16B
            int row = idx >> 2, seg = idx & 3;
            const __half* src = g_O + (m0 + row) * 256 + kc * 32 + seg * 8;
            CP_ASYNC16(base + row * 80 + seg * 16, src);
        }
    };
    auto cpB = [&](int kc, int buf) {
        uint32_t base = sb + 1024 + buf * 20480;
#pragma unroll
        for (int i = 0; i < 2; ++i) {
            int idx = tid + i * 256;                // 512 lines of 16B
            int row = idx >> 2, seg = idx & 3;
            const __half* sh = g_Wh + (long long)(n0 + row) * 256 + kc * 32 + seg * 8;
            CP_ASYNC16(base + 10240 + row * 80 + seg * 16, sh);
        }
    };
    auto mma_buf = [&](int buf) {
        const uint32_t bufb = sb + 1024 + buf * 20480;
#pragma unroll
        for (int ks = 0; ks < 2; ++ks) {
            uint32_t af[4][4], bm[2][4];
#pragma unroll
            for (int mf = 0; mf < 4; ++mf)
                ldm_x4(af[mf], bufb + aOff + mf * 16 * 80 + ks * 32);
#pragma unroll
            for (int p = 0; p < 2; ++p)
                ldm_x4(bm[p], bufb + bOff + p * 16 * 80 + ks * 32);
#pragma unroll
            for (int mf = 0; mf < 4; ++mf)
#pragma unroll
                for (int p = 0; p < 2; ++p) {
                    uint32_t b0[2] = {bm[p][0], bm[p][2]};
                    uint32_t b1[2] = {bm[p][1], bm[p][3]};
                    mma16816f16(acc[mf][2 * p + 0], af[mf], b0);
                    mma16816f16(acc[mf][2 * p + 1], af[mf], b1);
                }
        }
    };

    // ---- prologue ----
    if (SRCSEL == 1) {
        cpA16(0, 0);
        cpB(0, 0);
        CP_COMMIT();
        CP_WAIT0();
        __syncthreads();
    } else {
        float4 r[4];
        loadA_regs(0, r);
        cpB(0, 0);
        CP_COMMIT();
        stsA(0, r);
        CP_WAIT0();
        __syncthreads();
    }
    // ---- main loop: 8 k-chunks ----
#pragma unroll 1
    for (int kc = 0; kc < 8; ++kc) {
        const int buf = kc & 1;
        float4 r[4];
        if (kc < 7) {
            if (SRCSEL == 1) {
                cpA16(kc + 1, buf ^ 1);
                cpB(kc + 1, buf ^ 1);
                CP_COMMIT();
            } else {
                cpB(kc + 1, buf ^ 1);
                CP_COMMIT();
                loadA_regs(kc + 1, r);
            }
        }
        mma_buf(buf);
        if (kc < 7) {
            if (SRCSEL == 0) stsA(buf ^ 1, r);
            CP_WAIT0();
            __syncthreads();
        }
    }

    // ---- epilogue ----
#pragma unroll
    for (int mf = 0; mf < 4; ++mf) {
#pragma unroll
        for (int nf = 0; nf < 4; ++nf) {
            const int cn = wn * 32 + nf * 8 + tig * 2;
            const float b0 = sBias[cn], b1 = sBias[cn + 1];
            const long long r0 = m0 + wm * 64 + mf * 16 + g;
            float v0 = scale * (acc[mf][nf][0] + b0);
            float v1 = scale * (acc[mf][nf][1] + b1);
            float v2 = scale * (acc[mf][nf][2] + b0);
            float v3 = scale * (acc[mf][nf][3] + b1);
            if (DSTSEL == 2) {
                float* p0 = Cp + r0 * N + n0 + cn;
                float* p1 = Cp + (r0 + 8) * N + n0 + cn;
                *reinterpret_cast<float2*>(p0) = make_float2(v0, v1);
                *reinterpret_cast<float2*>(p1) = make_float2(v2, v3);
            } else {
                __half* C16 = (DSTSEL == 0) ? g_Q : g_KV;
                *reinterpret_cast<uint32_t*>(C16 + r0 * N + n0 + cn) = h2pack(v0, v1);
                *reinterpret_cast<uint32_t*>(C16 + (r0 + 8) * N + n0 + cn) = h2pack(v2, v3);
            }
        }
    }
}

// ---- attention via fp16 HMMA: block = 1 window (R10, unchanged) ---------------
#define ASM_TOTAL (40960 + 36864)

__global__ __launch_bounds__(512, 1)
void attn_mma() {
    extern __shared__ __align__(16) char smem[];
    __half* sK  = (__half*)smem;                 // [h][key][40]
    __half* sVt = (__half*)(smem + 40960);       // [h][d][72]

    const int w = blockIdx.x;
    const int tid = threadIdx.x;
    const __half* kvb = g_KV + (long long)w * 32768;

#pragma unroll
    for (int i = 0; i < 4; ++i) {
        int idx = tid + i * 512;
        int h   = idx >> 8;
        int rem = idx & 255;
        int key = rem >> 2;
        int d8  = (rem & 3) * 8;
        const __half* src = kvb + key * 512 + h * 32 + d8;
        *reinterpret_cast<uint4*>(sK + h * 2560 + key * 40 + d8) =
            *reinterpret_cast<const uint4*>(src);
        uint4 v4 = *reinterpret_cast<const uint4*>(src + 256);
        const __half* vh = reinterpret_cast<const __half*>(&v4);
        __half* vt = sVt + h * 2304 + key;
#pragma unroll
        for (int j = 0; j < 8; ++j) vt[(d8 + j) * 72] = vh[j];
    }
    __syncthreads();

    const int wid = tid >> 5, lane = tid & 31;
    const int g = lane >> 2, t = lane & 3;
    const int h = wid >> 1, mh = wid & 1;
    const __half* Kh = sK + h * 2560;
    const __half* Vh = sVt + h * 2304;

    uint32_t qf[2][2][4];
    const __half* qbase = g_Q + (long long)w * 16384 + h * 32;
#pragma unroll
    for (int mt = 0; mt < 2; ++mt) {
        const int R = (mh * 2 + mt) * 16 + g;
#pragma unroll
        for (int kb = 0; kb < 2; ++kb) {
            const int c = kb * 16 + t * 2;
            qf[mt][kb][0] = *reinterpret_cast<const uint32_t*>(qbase + R * 256 + c);
            qf[mt][kb][1] = *reinterpret_cast<const uint32_t*>(qbase + (R + 8) * 256 + c);
            qf[mt][kb][2] = *reinterpret_cast<const uint32_t*>(qbase + R * 256 + c + 8);
            qf[mt][kb][3] = *reinterpret_cast<const uint32_t*>(qbase + (R + 8) * 256 + c + 8);
        }
    }

    float S[2][8][4];
#pragma unroll
    for (int mt = 0; mt < 2; ++mt)
#pragma unroll
        for (int nb = 0; nb < 8; ++nb)
#pragma unroll
            for (int q = 0; q < 4; ++q) S[mt][nb][q] = 0.f;

#pragma unroll
    for (int nb = 0; nb < 8; ++nb) {
        uint32_t bf[2][2];
#pragma unroll
        for (int kb = 0; kb < 2; ++kb) {
            const __half* p = Kh + (8 * nb + g) * 40 + kb * 16 + t * 2;
            bf[kb][0] = *(const uint32_t*)p;
            bf[kb][1] = *(const uint32_t*)(p + 8);
        }
#pragma unroll
        for (int mt = 0; mt < 2; ++mt)
#pragma unroll
            for (int kb = 0; kb < 2; ++kb)
                mma16816f16(S[mt][nb], qf[mt][kb], bf[kb]);
    }

    const float* bb = g_bias + h * 4096;
#pragma unroll
    for (int mt = 0; mt < 2; ++mt) {
        const int R = (mh * 2 + mt) * 16 + g;
#pragma unroll
        for (int nb = 0; nb < 8; ++nb) {
            const int c = nb * 8 + t * 2;
            float2 b0 = *reinterpret_cast<const float2*>(bb + R * 64 + c);
            float2 b1 = *reinterpret_cast<const float2*>(bb + (R + 8) * 64 + c);
            S[mt][nb][0] += b0.x; S[mt][nb][1] += b0.y;
            S[mt][nb][2] += b1.x; S[mt][nb][3] += b1.y;
        }
    }

    float inv[2][2];
#pragma unroll
    for (int mt = 0; mt < 2; ++mt) {
        float m0 = -1e30f, m1 = -1e30f;
#pragma unroll
        for (int nb = 0; nb < 8; ++nb) {
            m0 = fmaxf(m0, fmaxf(S[mt][nb][0], S[mt][nb][1]));
            m1 = fmaxf(m1, fmaxf(S[mt][nb][2], S[mt][nb][3]));
        }
        m0 = fmaxf(m0, __shfl_xor_sync(0xFFFFFFFF, m0, 1));
        m0 = fmaxf(m0, __shfl_xor_sync(0xFFFFFFFF, m0, 2));
        m1 = fmaxf(m1, __shfl_xor_sync(0xFFFFFFFF, m1, 1));
        m1 = fmaxf(m1, __shfl_xor_sync(0xFFFFFFFF, m1, 2));
        float s0 = 0.f, s1 = 0.f;
#pragma unroll
        for (int nb = 0; nb < 8; ++nb) {
            S[mt][nb][0] = __expf(S[mt][nb][0] - m0);
            S[mt][nb][1] = __expf(S[mt][nb][1] - m0);
            S[mt][nb][2] = __expf(S[mt][nb][2] - m1);
            S[mt][nb][3] = __expf(S[mt][nb][3] - m1);
            s0 += S[mt][nb][0] + S[mt][nb][1];
            s1 += S[mt][nb][2] + S[mt][nb][3];
        }
        s0 += __shfl_xor_sync(0xFFFFFFFF, s0, 1);
        s0 += __shfl_xor_sync(0xFFFFFFFF, s0, 2);
        s1 += __shfl_xor_sync(0xFFFFFFFF, s1, 1);
        s1 += __shfl_xor_sync(0xFFFFFFFF, s1, 2);
        inv[mt][0] = 1.f / s0;
        inv[mt][1] = 1.f / s1;
    }

    uint32_t pf[2][4][4];
#pragma unroll
    for (int mt = 0; mt < 2; ++mt)
#pragma unroll
        for (int kb = 0; kb < 4; ++kb) {
            pf[mt][kb][0] = h2pack(S[mt][2 * kb][0],     S[mt][2 * kb][1]);
            pf[mt][kb][1] = h2pack(S[mt][2 * kb][2],     S[mt][2 * kb][3]);
            pf[mt][kb][2] = h2pack(S[mt][2 * kb + 1][0], S[mt][2 * kb + 1][1]);
            pf[mt][kb][3] = h2pack(S[mt][2 * kb + 1][2], S[mt][2 * kb + 1][3]);
        }

    float O[2][4][4];
#pragma unroll
    for (int mt = 0; mt < 2; ++mt)
#pragma unroll
        for (int nb = 0; nb < 4; ++nb)
#pragma unroll
            for (int q = 0; q < 4; ++q) O[mt][nb][q] = 0.f;

#pragma unroll
    for (int nb = 0; nb < 4; ++nb) {
        uint32_t vf[4][2];
#pragma unroll
        for (int kb = 0; kb < 4; ++kb) {
            const __half* p = Vh + (8 * nb + g) * 72 + kb * 16 + t * 2;
            vf[kb][0] = *(const uint32_t*)p;
            vf[kb][1] = *(const uint32_t*)(p + 8);
        }
#pragma unroll
        for (int mt = 0; mt < 2; ++mt)
#pragma unroll
            for (int kb = 0; kb < 4; ++kb)
                mma16816f16(O[mt][nb], pf[mt][kb], vf[kb]);
    }

    __half* ob = g_O + (long long)w * 16384 + h * 32;
#pragma unroll
    for (int mt = 0; mt < 2; ++mt) {
        const int R = (mh * 2 + mt) * 16 + g;
#pragma unroll
        for (int nb = 0; nb < 4; ++nb) {
            const int c = nb * 8 + t * 2;
            *reinterpret_cast<uint32_t*>(ob + R * 256 + c) =
                h2pack(O[mt][nb][0] * inv[mt][0], O[mt][nb][1] * inv[mt][0]);
            *reinterpret_cast<uint32_t*>(ob + (R + 8) * 256 + c) =
                h2pack(O[mt][nb][2] * inv[mt][1], O[mt][nb][3] * inv[mt][1]);
        }
    }
}

// ---------------------------------------------------------------------------
extern "C" void kernel_launch(void* const* d_in, const int* in_sizes, int n_in,
                              void* d_out, int out_size) {
    const float* xq  = (const float*)d_in[0];
    const float* xs  = (const float*)d_in[1];
    const float* Wq  = (const float*)d_in[2];
    const float* bq  = (const float*)d_in[3];
    const float* Wkv = (const float*)d_in[4];
    const float* bkv = (const float*)d_in[5];
    const float* bt  = (const float*)d_in[6];
    const float* Wp  = (const float*)d_in[7];
    const float* bp  = (const float*)d_in[8];
    float* out = (float*)d_out;

    const int M = in_sizes[0] / 256;            // 262144
    const int B = M / 64;                       // 4096
    const float scale = 0.17677669529663687f;   // 32^-0.5

    cudaFuncSetAttribute(gemm_tc<256, 0, 0>,
                         cudaFuncAttributeMaxDynamicSharedMemorySize, GSM_TOTAL);
    cudaFuncSetAttribute(gemm_tc<512, 1, 0>,
                         cudaFuncAttributeMaxDynamicSharedMemorySize, GSM_TOTAL);
    cudaFuncSetAttribute(gemm_tc<256, 2, 1>,
                         cudaFuncAttributeMaxDynamicSharedMemorySize, GSM_TOTAL);
    cudaFuncSetAttribute(attn_mma,
                         cudaFuncAttributeMaxDynamicSharedMemorySize, ASM_TOTAL);

    bias_kernel<<<128, 256>>>(bt);

    convw_kernel<<<256, 256>>>(Wq, 256);
    gemm_tc<256, 0, 0><<<dim3(2, M / 128), 256, GSM_TOTAL>>>(xq, bq, nullptr, scale);

    convw_kernel<<<512, 256>>>(Wkv, 512);
    gemm_tc<512, 1, 0><<<dim3(4, M / 128), 256, GSM_TOTAL>>>(xs, bkv, nullptr, 1.f);

    attn_mma<<<B, 512, ASM_TOTAL>>>();

    convw_kernel<<<256, 256>>>(Wp, 256);
    gemm_tc<256, 2, 1><<<dim3(2, M / 128), 256, GSM_TOTAL>>>(nullptr, bp, out, 1.f);
}

// round 13
// speedup vs baseline: 2.9536x; 1.0073x over previous
#include <cuda_runtime.h>
#include <cuda_fp16.h>
#include <cstdint>

// ---------------------------------------------------------------------------
// WindowedCrossAttention — R13 (= R12 resubmitted; R12 failed on an infra
// flake: "device busy" at harness init, before any kernel code ran)
//   GEMM: 3-stage circular cp.async pipeline (wait_group 1 in steady state) —
//   oldest chunk only must land before MMA; newest flies through compute.
//   Attention: 256-thread blocks (4 heads), launch_bounds(256,2) — two barrier
//   domains per SM (R11's proven lever applied to attention).
// ---------------------------------------------------------------------------

__device__ __half g_Q [4096ull * 64ull * 256ull];
__device__ __half g_KV[4096ull * 64ull * 512ull];
__device__ __half g_O [4096ull * 64ull * 256ull];
__device__ float  g_bias[8 * 64 * 64];                // [h][q][k]
__device__ __half g_Wh[512 * 256];                    // fp16(W), [n][k]

// ---- helpers ----------------------------------------------------------------
__device__ __forceinline__ uint32_t smem_u32(const void* p) {
    uint32_t a;
    asm("{ .reg .u64 t; cvta.to.shared.u64 t, %1; cvt.u32.u64 %0, t; }" : "=r"(a) : "l"(p));
    return a;
}
__device__ __forceinline__ void mma16816f16(float* c, const uint32_t* a, const uint32_t* b) {
    asm volatile(
        "mma.sync.aligned.m16n8k16.row.col.f32.f16.f16.f32 "
        "{%0,%1,%2,%3}, {%4,%5,%6,%7}, {%8,%9}, {%0,%1,%2,%3};"
        : "+f"(c[0]), "+f"(c[1]), "+f"(c[2]), "+f"(c[3])
        : "r"(a[0]), "r"(a[1]), "r"(a[2]), "r"(a[3]), "r"(b[0]), "r"(b[1]));
}
__device__ __forceinline__ void ldm_x4(uint32_t* r, uint32_t addr) {
    asm volatile("ldmatrix.sync.aligned.m8n8.x4.shared.b16 {%0,%1,%2,%3}, [%4];"
                 : "=r"(r[0]), "=r"(r[1]), "=r"(r[2]), "=r"(r[3]) : "r"(addr));
}
__device__ __forceinline__ uint32_t h2pack(float a, float b) {
    __half2 h = __floats2half2_rn(a, b);
    return *reinterpret_cast<uint32_t*>(&h);
}
#define CP_ASYNC16(dst, src) \
    asm volatile("cp.async.cg.shared.global [%0], [%1], 16;" :: "r"(dst), "l"(src))
#define CP_COMMIT() asm volatile("cp.async.commit_group;")
#define CP_WAIT0()  asm volatile("cp.async.wait_group 0;")
#define CP_WAIT1()  asm volatile("cp.async.wait_group 1;")

// ---- relative-position bias: g_bias[h][q][k] = bt[rel(q,k)][h] ---------------
__global__ void bias_kernel(const float* __restrict__ bt) {
    int idx = blockIdx.x * 256 + threadIdx.x;
    if (idx >= 8 * 64 * 64) return;
    int h  = idx >> 12;
    int nm = idx & 4095;
    int q = nm >> 6, k = nm & 63;
    int dy = (q >> 3) - (k >> 3);
    int dx = (q & 7) - (k & 7);
    int r  = (dy + 7) * 15 + (dx + 7);
    g_bias[idx] = bt[r * 8 + h];
}

// ---- W -> fp16, transposed [n][k] --------------------------------------------
__global__ void convw_kernel(const float* __restrict__ W, int Ncols) {
    int idx = blockIdx.x * 256 + threadIdx.x;
    if (idx >= Ncols * 256) return;
    int n = idx >> 8;
    int k = idx & 255;
    g_Wh[idx] = __float2half_rn(W[k * Ncols + n]);
}

// ---- single-pass fp16 GEMM, 3-stage pipeline ---------------------------------
// 256 threads, 8 warps (2m x 4n), warp tile 64x32, block tile 128x128, KC=32.
// Buffers (base = 1024 + buf*20480, buf in {0,1,2}): A16@0  Wh@10240
//   rows padded to 40 halves (80B).
#define GSM_TOTAL (1024 + 3 * 20480)

template <int N, int DSTSEL, int SRCSEL>
__global__ __launch_bounds__(256, 2)
void gemm_tc(const float* __restrict__ Ap, const float* __restrict__ bias,
             float* __restrict__ Cp, float scale) {
    extern __shared__ __align__(1024) char smem[];
    const uint32_t sb = smem_u32(smem);

    const int tid  = threadIdx.x;
    const int wid  = tid >> 5, lane = tid & 31;
    const int g    = lane >> 2, tig = lane & 3;
    const int wm   = wid & 1, wn = wid >> 1;       // 2x4 warp grid
    const int n0   = blockIdx.x * 128;
    const long long m0 = (long long)blockIdx.y * 128;

    float* sBias = (float*)smem;
    if (tid < 128) sBias[tid] = bias[n0 + tid];

    float acc[4][4][4];                             // warp tile 64x32
#pragma unroll
    for (int i = 0; i < 4; ++i)
#pragma unroll
        for (int j = 0; j < 4; ++j)
#pragma unroll
            for (int q = 0; q < 4; ++q) acc[i][j][q] = 0.f;

    const uint32_t lrow = lane & 15, lcol = (lane >> 4) * 8;
    const uint32_t aOff = (wm * 64 + lrow) * 80 + lcol * 2;
    const uint32_t bOff = 10240 + (wn * 32 + lrow) * 80 + lcol * 2;

    auto loadA_regs = [&](int kc, float4* r) {
#pragma unroll
        for (int i = 0; i < 4; ++i) {
            int idx = tid + i * 256;                // 1024 float4
            int row = idx >> 3;
            int q = idx & 7;
            r[i] = *reinterpret_cast<const float4*>(
                Ap + (m0 + row) * 256 + kc * 32 + q * 4);
        }
    };
    auto stsA = [&](int buf, const float4* r) {
        char* base = smem + 1024 + buf * 20480;
#pragma unroll
        for (int i = 0; i < 4; ++i) {
            int idx = tid + i * 256;
            int row = idx >> 3;
            int q = idx & 7;
            float4 v = r[i];
            __half2 p0 = __floats2half2_rn(v.x, v.y);
            __half2 p1 = __floats2half2_rn(v.z, v.w);
            *reinterpret_cast<uint2*>(base + row * 80 + q * 8) =
                make_uint2(*reinterpret_cast<uint32_t*>(&p0),
                           *reinterpret_cast<uint32_t*>(&p1));
        }
    };
    auto cpA16 = [&](int kc, int buf) {             // SRCSEL==1: A = g_O fp16
        uint32_t base = sb + 1024 + buf * 20480;
#pragma unroll
        for (int i = 0; i < 2; ++i) {
            int idx = tid + i * 256;                // 512 lines of 16B
            int row = idx >> 2, seg = idx & 3;
            const __half* src = g_O + (m0 + row) * 256 + kc * 32 + seg * 8;
            CP_ASYNC16(base + row * 80 + seg * 16, src);
        }
    };
    auto cpB = [&](int kc, int buf) {
        uint32_t base = sb + 1024 + buf * 20480;
#pragma unroll
        for (int i = 0; i < 2; ++i) {
            int idx = tid + i * 256;                // 512 lines of 16B
            int row = idx >> 2, seg = idx & 3;
            const __half* sh = g_Wh + (long long)(n0 + row) * 256 + kc * 32 + seg * 8;
            CP_ASYNC16(base + 10240 + row * 80 + seg * 16, sh);
        }
    };
    auto mma_buf = [&](int buf) {
        const uint32_t bufb = sb + 1024 + buf * 20480;
#pragma unroll
        for (int ks = 0; ks < 2; ++ks) {
            uint32_t af[4][4], bm[2][4];
#pragma unroll
            for (int mf = 0; mf < 4; ++mf)
                ldm_x4(af[mf], bufb + aOff + mf * 16 * 80 + ks * 32);
#pragma unroll
            for (int p = 0; p < 2; ++p)
                ldm_x4(bm[p], bufb + bOff + p * 16 * 80 + ks * 32);
#pragma unroll
            for (int mf = 0; mf < 4; ++mf)
#pragma unroll
                for (int p = 0; p < 2; ++p) {
                    uint32_t b0[2] = {bm[p][0], bm[p][2]};
                    uint32_t b1[2] = {bm[p][1], bm[p][3]};
                    mma16816f16(acc[mf][2 * p + 0], af[mf], b0);
                    mma16816f16(acc[mf][2 * p + 1], af[mf], b1);
                }
        }
    };
    auto load_chunk = [&](int kc) {                 // prologue only
        int buf = kc % 3;
        if (SRCSEL == 1) {
            cpA16(kc, buf);
        } else {
            float4 r[4];
            loadA_regs(kc, r);
            stsA(buf, r);
        }
        cpB(kc, buf);
        CP_COMMIT();
    };

    // ---- prologue: chunks 0 and 1 in flight ----
    load_chunk(0);
    load_chunk(1);

    // ---- main loop: 8 k-chunks, 3-stage ----
#pragma unroll 1
    for (int kc = 0; kc < 8; ++kc) {
        float4 r[4];
        const bool pre = (kc < 6);
        if (pre && SRCSEL == 0) loadA_regs(kc + 2, r);   // LDG early
        if (kc < 7) CP_WAIT1(); else CP_WAIT0();         // oldest group only
        __syncthreads();
        if (pre) {
            const int nbuf = (kc + 2) % 3;
            if (SRCSEL == 1) cpA16(kc + 2, nbuf);
            else             stsA(nbuf, r);
            cpB(kc + 2, nbuf);
            CP_COMMIT();
        }
        mma_buf(kc % 3);
    }

    // ---- epilogue ----
#pragma unroll
    for (int mf = 0; mf < 4; ++mf) {
#pragma unroll
        for (int nf = 0; nf < 4; ++nf) {
            const int cn = wn * 32 + nf * 8 + tig * 2;
            const float b0 = sBias[cn], b1 = sBias[cn + 1];
            const long long r0 = m0 + wm * 64 + mf * 16 + g;
            float v0 = scale * (acc[mf][nf][0] + b0);
            float v1 = scale * (acc[mf][nf][1] + b1);
            float v2 = scale * (acc[mf][nf][2] + b0);
            float v3 = scale * (acc[mf][nf][3] + b1);
            if (DSTSEL == 2) {
                float* p0 = Cp + r0 * N + n0 + cn;
                float* p1 = Cp + (r0 + 8) * N + n0 + cn;
                *reinterpret_cast<float2*>(p0) = make_float2(v0, v1);
                *reinterpret_cast<float2*>(p1) = make_float2(v2, v3);
            } else {
                __half* C16 = (DSTSEL == 0) ? g_Q : g_KV;
                *reinterpret_cast<uint32_t*>(C16 + r0 * N + n0 + cn) = h2pack(v0, v1);
                *reinterpret_cast<uint32_t*>(C16 + (r0 + 8) * N + n0 + cn) = h2pack(v2, v3);
            }
        }
    }
}

// ---- attention via fp16 HMMA: block = 4 heads of 1 window ---------------------
// grid (B, 2); smem: sK [4][64][40] (20480 B) + sVt [4][32][72] (18432 B)
#define ASM_TOTAL (20480 + 18432)

__global__ __launch_bounds__(256, 2)
void attn_mma() {
    extern __shared__ __align__(16) char smem[];
    __half* sK  = (__half*)smem;                 // [hl][key][40]
    __half* sVt = (__half*)(smem + 20480);       // [hl][d][72]

    const int w  = blockIdx.x;
    const int hg = blockIdx.y;                   // head group: heads hg*4..hg*4+3
    const int tid = threadIdx.x;
    const __half* kvb = g_KV + (long long)w * 32768 + hg * 128;

    // stage K (raw uint4) and V (transpose scatter); 1024 uint4 each side
#pragma unroll
    for (int i = 0; i < 4; ++i) {
        int idx = tid + i * 256;                 // 0..1023
        int hl  = idx >> 8;                      // 0..3
        int rem = idx & 255;
        int key = rem >> 2;
        int d8  = (rem & 3) * 8;
        const __half* src = kvb + key * 512 + hl * 32 + d8;
        *reinterpret_cast<uint4*>(sK + hl * 2560 + key * 40 + d8) =
            *reinterpret_cast<const uint4*>(src);
        uint4 v4 = *reinterpret_cast<const uint4*>(src + 256);
        const __half* vh = reinterpret_cast<const __half*>(&v4);
        __half* vt = sVt + hl * 2304 + key;
#pragma unroll
        for (int j = 0; j < 8; ++j) vt[(d8 + j) * 72] = vh[j];
    }
    __syncthreads();

    const int wid = tid >> 5, lane = tid & 31;
    const int g = lane >> 2, t = lane & 3;
    const int hl = wid >> 1, mh = wid & 1;       // local head, query half
    const int h  = hg * 4 + hl;
    const __half* Kh = sK + hl * 2560;
    const __half* Vh = sVt + hl * 2304;

    uint32_t qf[2][2][4];
    const __half* qbase = g_Q + (long long)w * 16384 + h * 32;
#pragma unroll
    for (int mt = 0; mt < 2; ++mt) {
        const int R = (mh * 2 + mt) * 16 + g;
#pragma unroll
        for (int kb = 0; kb < 2; ++kb) {
            const int c = kb * 16 + t * 2;
            qf[mt][kb][0] = *reinterpret_cast<const uint32_t*>(qbase + R * 256 + c);
            qf[mt][kb][1] = *reinterpret_cast<const uint32_t*>(qbase + (R + 8) * 256 + c);
            qf[mt][kb][2] = *reinterpret_cast<const uint32_t*>(qbase + R * 256 + c + 8);
            qf[mt][kb][3] = *reinterpret_cast<const uint32_t*>(qbase + (R + 8) * 256 + c + 8);
        }
    }

    float S[2][8][4];
#pragma unroll
    for (int mt = 0; mt < 2; ++mt)
#pragma unroll
        for (int nb = 0; nb < 8; ++nb)
#pragma unroll
            for (int q = 0; q < 4; ++q) S[mt][nb][q] = 0.f;

#pragma unroll
    for (int nb = 0; nb < 8; ++nb) {
        uint32_t bf[2][2];
#pragma unroll
        for (int kb = 0; kb < 2; ++kb) {
            const __half* p = Kh + (8 * nb + g) * 40 + kb * 16 + t * 2;
            bf[kb][0] = *(const uint32_t*)p;
            bf[kb][1] = *(const uint32_t*)(p + 8);
        }
#pragma unroll
        for (int mt = 0; mt < 2; ++mt)
#pragma unroll
            for (int kb = 0; kb < 2; ++kb)
                mma16816f16(S[mt][nb], qf[mt][kb], bf[kb]);
    }

    const float* bb = g_bias + h * 4096;
#pragma unroll
    for (int mt = 0; mt < 2; ++mt) {
        const int R = (mh * 2 + mt) * 16 + g;
#pragma unroll
        for (int nb = 0; nb < 8; ++nb) {
            const int c = nb * 8 + t * 2;
            float2 b0 = *reinterpret_cast<const float2*>(bb + R * 64 + c);
            float2 b1 = *reinterpret_cast<const float2*>(bb + (R + 8) * 64 + c);
            S[mt][nb][0] += b0.x; S[mt][nb][1] += b0.y;
            S[mt][nb][2] += b1.x; S[mt][nb][3] += b1.y;
        }
    }

    float inv[2][2];
#pragma unroll
    for (int mt = 0; mt < 2; ++mt) {
        float m0 = -1e30f, m1 = -1e30f;
#pragma unroll
        for (int nb = 0; nb < 8; ++nb) {
            m0 = fmaxf(m0, fmaxf(S[mt][nb][0], S[mt][nb][1]));
            m1 = fmaxf(m1, fmaxf(S[mt][nb][2], S[mt][nb][3]));
        }
        m0 = fmaxf(m0, __shfl_xor_sync(0xFFFFFFFF, m0, 1));
        m0 = fmaxf(m0, __shfl_xor_sync(0xFFFFFFFF, m0, 2));
        m1 = fmaxf(m1, __shfl_xor_sync(0xFFFFFFFF, m1, 1));
        m1 = fmaxf(m1, __shfl_xor_sync(0xFFFFFFFF, m1, 2));
        float s0 = 0.f, s1 = 0.f;
#pragma unroll
        for (int nb = 0; nb < 8; ++nb) {
            S[mt][nb][0] = __expf(S[mt][nb][0] - m0);
            S[mt][nb][1] = __expf(S[mt][nb][1] - m0);
            S[mt][nb][2] = __expf(S[mt][nb][2] - m1);
            S[mt][nb][3] = __expf(S[mt][nb][3] - m1);
            s0 += S[mt][nb][0] + S[mt][nb][1];
            s1 += S[mt][nb][2] + S[mt][nb][3];
        }
        s0 += __shfl_xor_sync(0xFFFFFFFF, s0, 1);
        s0 += __shfl_xor_sync(0xFFFFFFFF, s0, 2);
        s1 += __shfl_xor_sync(0xFFFFFFFF, s1, 1);
        s1 += __shfl_xor_sync(0xFFFFFFFF, s1, 2);
        inv[mt][0] = 1.f / s0;
        inv[mt][1] = 1.f / s1;
    }

    uint32_t pf[2][4][4];
#pragma unroll
    for (int mt = 0; mt < 2; ++mt)
#pragma unroll
        for (int kb = 0; kb < 4; ++kb) {
            pf[mt][kb][0] = h2pack(S[mt][2 * kb][0],     S[mt][2 * kb][1]);
            pf[mt][kb][1] = h2pack(S[mt][2 * kb][2],     S[mt][2 * kb][3]);
            pf[mt][kb][2] = h2pack(S[mt][2 * kb + 1][0], S[mt][2 * kb + 1][1]);
            pf[mt][kb][3] = h2pack(S[mt][2 * kb + 1][2], S[mt][2 * kb + 1][3]);
        }

    float O[2][4][4];
#pragma unroll
    for (int mt = 0; mt < 2; ++mt)
#pragma unroll
        for (int nb = 0; nb < 4; ++nb)
#pragma unroll
            for (int q = 0; q < 4; ++q) O[mt][nb][q] = 0.f;

#pragma unroll
    for (int nb = 0; nb < 4; ++nb) {
        uint32_t vf[4][2];
#pragma unroll
        for (int kb = 0; kb < 4; ++kb) {
            const __half* p = Vh + (8 * nb + g) * 72 + kb * 16 + t * 2;
            vf[kb][0] = *(const uint32_t*)p;
            vf[kb][1] = *(const uint32_t*)(p + 8);
        }
#pragma unroll
        for (int mt = 0; mt < 2; ++mt)
#pragma unroll
            for (int kb = 0; kb < 4; ++kb)
                mma16816f16(O[mt][nb], pf[mt][kb], vf[kb]);
    }

    __half* ob = g_O + (long long)w * 16384 + h * 32;
#pragma unroll
    for (int mt = 0; mt < 2; ++mt) {
        const int R = (mh * 2 + mt) * 16 + g;
#pragma unroll
        for (int nb = 0; nb < 4; ++nb) {
            const int c = nb * 8 + t * 2;
            *reinterpret_cast<uint32_t*>(ob + R * 256 + c) =
                h2pack(O[mt][nb][0] * inv[mt][0], O[mt][nb][1] * inv[mt][0]);
            *reinterpret_cast<uint32_t*>(ob + (R + 8) * 256 + c) =
                h2pack(O[mt][nb][2] * inv[mt][1], O[mt][nb][3] * inv[mt][1]);
        }
    }
}

// ---------------------------------------------------------------------------
extern "C" void kernel_launch(void* const* d_in, const int* in_sizes, int n_in,
                              void* d_out, int out_size) {
    const float* xq  = (const float*)d_in[0];
    const float* xs  = (const float*)d_in[1];
    const float* Wq  = (const float*)d_in[2];
    const float* bq  = (const float*)d_in[3];
    const float* Wkv = (const float*)d_in[4];
    const float* bkv = (const float*)d_in[5];
    const float* bt  = (const float*)d_in[6];
    const float* Wp  = (const float*)d_in[7];
    const float* bp  = (const float*)d_in[8];
    float* out = (float*)d_out;

    const int M = in_sizes[0] / 256;            // 262144
    const int B = M / 64;                       // 4096
    const float scale = 0.17677669529663687f;   // 32^-0.5

    cudaFuncSetAttribute(gemm_tc<256, 0, 0>,
                         cudaFuncAttributeMaxDynamicSharedMemorySize, GSM_TOTAL);
    cudaFuncSetAttribute(gemm_tc<512, 1, 0>,
                         cudaFuncAttributeMaxDynamicSharedMemorySize, GSM_TOTAL);
    cudaFuncSetAttribute(gemm_tc<256, 2, 1>,
                         cudaFuncAttributeMaxDynamicSharedMemorySize, GSM_TOTAL);
    cudaFuncSetAttribute(attn_mma,
                         cudaFuncAttributeMaxDynamicSharedMemorySize, ASM_TOTAL);

    bias_kernel<<<128, 256>>>(bt);

    convw_kernel<<<256, 256>>>(Wq, 256);
    gemm_tc<256, 0, 0><<<dim3(2, M / 128), 256, GSM_TOTAL>>>(xq, bq, nullptr, scale);

    convw_kernel<<<512, 256>>>(Wkv, 512);
    gemm_tc<512, 1, 0><<<dim3(4, M / 128), 256, GSM_TOTAL>>>(xs, bkv, nullptr, 1.f);

    attn_mma<<<dim3(B, 2), 256, ASM_TOTAL>>>();

    convw_kernel<<<256, 256>>>(Wp, 256);
    gemm_tc<256, 2, 1><<<dim3(2, M / 128), 256, GSM_TOTAL>>>(nullptr, bp, out, 1.f);
}

// round 14
// speedup vs baseline: 2.9975x; 1.0149x over previous
#include <cuda_runtime.h>
#include <cuda_fp16.h>
#include <cstdint>

// ---------------------------------------------------------------------------
// WindowedCrossAttention — R14
//   GEMM: KC=64 (4 chunks, half the chunk-boundary overhead), 3-stage ring,
//   smem 111.6 KB/block at occupancy 2 (223/228 KB). All W pre-transposed into
//   ONE fp16 array [1024][256] by a single fused convw launch hoisted upfront.
//   Attention: R13 unchanged.
// ---------------------------------------------------------------------------

__device__ __half g_Q [4096ull * 64ull * 256ull];
__device__ __half g_KV[4096ull * 64ull * 512ull];
__device__ __half g_O [4096ull * 64ull * 256ull];
__device__ float  g_bias[8 * 64 * 64];                // [h][q][k]
__device__ __half g_Wh[1024 * 256];                   // [n][k]: Wq@0, Wkv@256, Wp@768

// ---- helpers ----------------------------------------------------------------
__device__ __forceinline__ uint32_t smem_u32(const void* p) {
    uint32_t a;
    asm("{ .reg .u64 t; cvta.to.shared.u64 t, %1; cvt.u32.u64 %0, t; }" : "=r"(a) : "l"(p));
    return a;
}
__device__ __forceinline__ void mma16816f16(float* c, const uint32_t* a, const uint32_t* b) {
    asm volatile(
        "mma.sync.aligned.m16n8k16.row.col.f32.f16.f16.f32 "
        "{%0,%1,%2,%3}, {%4,%5,%6,%7}, {%8,%9}, {%0,%1,%2,%3};"
        : "+f"(c[0]), "+f"(c[1]), "+f"(c[2]), "+f"(c[3])
        : "r"(a[0]), "r"(a[1]), "r"(a[2]), "r"(a[3]), "r"(b[0]), "r"(b[1]));
}
__device__ __forceinline__ void ldm_x4(uint32_t* r, uint32_t addr) {
    asm volatile("ldmatrix.sync.aligned.m8n8.x4.shared.b16 {%0,%1,%2,%3}, [%4];"
                 : "=r"(r[0]), "=r"(r[1]), "=r"(r[2]), "=r"(r[3]) : "r"(addr));
}
__device__ __forceinline__ uint32_t h2pack(float a, float b) {
    __half2 h = __floats2half2_rn(a, b);
    return *reinterpret_cast<uint32_t*>(&h);
}
#define CP_ASYNC16(dst, src) \
    asm volatile("cp.async.cg.shared.global [%0], [%1], 16;" :: "r"(dst), "l"(src))
#define CP_COMMIT() asm volatile("cp.async.commit_group;")
#define CP_WAIT0()  asm volatile("cp.async.wait_group 0;")
#define CP_WAIT1()  asm volatile("cp.async.wait_group 1;")

// ---- relative-position bias: g_bias[h][q][k] = bt[rel(q,k)][h] ---------------
__global__ void bias_kernel(const float* __restrict__ bt) {
    int idx = blockIdx.x * 256 + threadIdx.x;
    if (idx >= 8 * 64 * 64) return;
    int h  = idx >> 12;
    int nm = idx & 4095;
    int q = nm >> 6, k = nm & 63;
    int dy = (q >> 3) - (k >> 3);
    int dx = (q & 7) - (k & 7);
    int r  = (dy + 7) * 15 + (dx + 7);
    g_bias[idx] = bt[r * 8 + h];
}

// ---- fused W transpose: Wq/Wkv/Wp -> g_Wh[1024][256] fp16 --------------------
__global__ void convw_all(const float* __restrict__ Wq,
                          const float* __restrict__ Wkv,
                          const float* __restrict__ Wp) {
    int idx = blockIdx.x * 256 + threadIdx.x;     // 0 .. 262143
    if (idx >= 1024 * 256) return;
    int n = idx >> 8;                              // global output row 0..1023
    int k = idx & 255;
    float v;
    if (n < 256)       v = Wq [k * 256 + n];
    else if (n < 768)  v = Wkv[k * 512 + (n - 256)];
    else               v = Wp [k * 256 + (n - 768)];
    g_Wh[idx] = __float2half_rn(v);
}

// ---- single-pass fp16 GEMM, KC=64, 3-stage ring -------------------------------
// 256 threads, 8 warps (2m x 4n), warp tile 64x32, block tile 128x128.
// Buffers (base = 1024 + buf*36864, buf in {0,1,2}): A16@0  Wh@18432
//   rows padded to 72 halves (144 B).
#define GSM_TOTAL (1024 + 3 * 36864)

template <int N, int DSTSEL, int SRCSEL>
__global__ __launch_bounds__(256, 2)
void gemm_tc(const float* __restrict__ Ap, const float* __restrict__ bias,
             float* __restrict__ Cp, float scale, int woff) {
    extern __shared__ __align__(1024) char smem[];
    const uint32_t sb = smem_u32(smem);

    const int tid  = threadIdx.x;
    const int wid  = tid >> 5, lane = tid & 31;
    const int g    = lane >> 2, tig = lane & 3;
    const int wm   = wid & 1, wn = wid >> 1;       // 2x4 warp grid
    const int n0   = blockIdx.x * 128;
    const long long m0 = (long long)blockIdx.y * 128;

    float* sBias = (float*)smem;
    if (tid < 128) sBias[tid] = bias[n0 + tid];

    float acc[4][4][4];                             // warp tile 64x32
#pragma unroll
    for (int i = 0; i < 4; ++i)
#pragma unroll
        for (int j = 0; j < 4; ++j)
#pragma unroll
            for (int q = 0; q < 4; ++q) acc[i][j][q] = 0.f;

    const uint32_t lrow = lane & 15, lcol = (lane >> 4) * 8;
    const uint32_t aOff = (wm * 64 + lrow) * 144 + lcol * 2;
    const uint32_t bOff = 18432 + (wn * 32 + lrow) * 144 + lcol * 2;

    auto loadA_regs = [&](int kc, float4* r) {      // 2048 float4 per chunk
#pragma unroll
        for (int i = 0; i < 8; ++i) {
            int idx = tid + i * 256;
            int row = idx >> 4;                     // 16 float4 per 64-float row
            int q = idx & 15;
            r[i] = *reinterpret_cast<const float4*>(
                Ap + (m0 + row) * 256 + kc * 64 + q * 4);
        }
    };
    auto stsA = [&](int buf, const float4* r) {
        char* base = smem + 1024 + buf * 36864;
#pragma unroll
        for (int i = 0; i < 8; ++i) {
            int idx = tid + i * 256;
            int row = idx >> 4;
            int q = idx & 15;
            float4 v = r[i];
            __half2 p0 = __floats2half2_rn(v.x, v.y);
            __half2 p1 = __floats2half2_rn(v.z, v.w);
            *reinterpret_cast<uint2*>(base + row * 144 + q * 8) =
                make_uint2(*reinterpret_cast<uint32_t*>(&p0),
                           *reinterpret_cast<uint32_t*>(&p1));
        }
    };
    auto cpA16 = [&](int kc, int buf) {             // SRCSEL==1: A = g_O fp16
        uint32_t base = sb + 1024 + buf * 36864;
#pragma unroll
        for (int i = 0; i < 4; ++i) {
            int idx = tid + i * 256;                // 1024 lines of 16B
            int row = idx >> 3, seg = idx & 7;
            const __half* src = g_O + (m0 + row) * 256 + kc * 64 + seg * 8;
            CP_ASYNC16(base + row * 144 + seg * 16, src);
        }
    };
    auto cpB = [&](int kc, int buf) {
        uint32_t base = sb + 1024 + buf * 36864;
#pragma unroll
        for (int i = 0; i < 4; ++i) {
            int idx = tid + i * 256;                // 1024 lines of 16B
            int row = idx >> 3, seg = idx & 7;
            const __half* sh = g_Wh + (long long)(woff + n0 + row) * 256 + kc * 64 + seg * 8;
            CP_ASYNC16(base + 18432 + row * 144 + seg * 16, sh);
        }
    };
    auto mma_buf = [&](int buf) {
        const uint32_t bufb = sb + 1024 + buf * 36864;
#pragma unroll
        for (int ks = 0; ks < 4; ++ks) {
            uint32_t af[4][4], bm[2][4];
#pragma unroll
            for (int mf = 0; mf < 4; ++mf)
                ldm_x4(af[mf], bufb + aOff + mf * 16 * 144 + ks * 32);
#pragma unroll
            for (int p = 0; p < 2; ++p)
                ldm_x4(bm[p], bufb + bOff + p * 16 * 144 + ks * 32);
#pragma unroll
            for (int mf = 0; mf < 4; ++mf)
#pragma unroll
                for (int p = 0; p < 2; ++p) {
                    uint32_t b0[2] = {bm[p][0], bm[p][2]};
                    uint32_t b1[2] = {bm[p][1], bm[p][3]};
                    mma16816f16(acc[mf][2 * p + 0], af[mf], b0);
                    mma16816f16(acc[mf][2 * p + 1], af[mf], b1);
                }
        }
    };
    auto load_chunk = [&](int kc) {                 // prologue only
        int buf = kc % 3;
        if (SRCSEL == 1) {
            cpA16(kc, buf);
        } else {
            float4 r[8];
            loadA_regs(kc, r);
            stsA(buf, r);
        }
        cpB(kc, buf);
        CP_COMMIT();
    };

    // ---- prologue: chunks 0 and 1 in flight ----
    load_chunk(0);
    load_chunk(1);

    // ---- main loop: 4 k-chunks, 3-stage ----
#pragma unroll 1
    for (int kc = 0; kc < 4; ++kc) {
        float4 r[8];
        const bool pre = (kc < 2);
        if (pre && SRCSEL == 0) loadA_regs(kc + 2, r);   // LDG early
        if (kc < 3) CP_WAIT1(); else CP_WAIT0();         // oldest group only
        __syncthreads();
        if (pre) {
            const int nbuf = (kc + 2) % 3;
            if (SRCSEL == 1) cpA16(kc + 2, nbuf);
            else             stsA(nbuf, r);
            cpB(kc + 2, nbuf);
            CP_COMMIT();
        }
        mma_buf(kc % 3);
    }

    // ---- epilogue ----
#pragma unroll
    for (int mf = 0; mf < 4; ++mf) {
#pragma unroll
        for (int nf = 0; nf < 4; ++nf) {
            const int cn = wn * 32 + nf * 8 + tig * 2;
            const float b0 = sBias[cn], b1 = sBias[cn + 1];
            const long long r0 = m0 + wm * 64 + mf * 16 + g;
            float v0 = scale * (acc[mf][nf][0] + b0);
            float v1 = scale * (acc[mf][nf][1] + b1);
            float v2 = scale * (acc[mf][nf][2] + b0);
            float v3 = scale * (acc[mf][nf][3] + b1);
            if (DSTSEL == 2) {
                float* p0 = Cp + r0 * N + n0 + cn;
                float* p1 = Cp + (r0 + 8) * N + n0 + cn;
                *reinterpret_cast<float2*>(p0) = make_float2(v0, v1);
                *reinterpret_cast<float2*>(p1) = make_float2(v2, v3);
            } else {
                __half* C16 = (DSTSEL == 0) ? g_Q : g_KV;
                *reinterpret_cast<uint32_t*>(C16 + r0 * N + n0 + cn) = h2pack(v0, v1);
                *reinterpret_cast<uint32_t*>(C16 + (r0 + 8) * N + n0 + cn) = h2pack(v2, v3);
            }
        }
    }
}

// ---- attention via fp16 HMMA: block = 4 heads of 1 window (R13 unchanged) -----
#define ASM_TOTAL (20480 + 18432)

__global__ __launch_bounds__(256, 2)
void attn_mma() {
    extern __shared__ __align__(16) char smem[];
    __half* sK  = (__half*)smem;                 // [hl][key][40]
    __half* sVt = (__half*)(smem + 20480);       // [hl][d][72]

    const int w  = blockIdx.x;
    const int hg = blockIdx.y;                   // head group: heads hg*4..hg*4+3
    const int tid = threadIdx.x;
    const __half* kvb = g_KV + (long long)w * 32768 + hg * 128;

#pragma unroll
    for (int i = 0; i < 4; ++i) {
        int idx = tid + i * 256;                 // 0..1023
        int hl  = idx >> 8;
        int rem = idx & 255;
        int key = rem >> 2;
        int d8  = (rem & 3) * 8;
        const __half* src = kvb + key * 512 + hl * 32 + d8;
        *reinterpret_cast<uint4*>(sK + hl * 2560 + key * 40 + d8) =
            *reinterpret_cast<const uint4*>(src);
        uint4 v4 = *reinterpret_cast<const uint4*>(src + 256);
        const __half* vh = reinterpret_cast<const __half*>(&v4);
        __half* vt = sVt + hl * 2304 + key;
#pragma unroll
        for (int j = 0; j < 8; ++j) vt[(d8 + j) * 72] = vh[j];
    }
    __syncthreads();

    const int wid = tid >> 5, lane = tid & 31;
    const int g = lane >> 2, t = lane & 3;
    const int hl = wid >> 1, mh = wid & 1;
    const int h  = hg * 4 + hl;
    const __half* Kh = sK + hl * 2560;
    const __half* Vh = sVt + hl * 2304;

    uint32_t qf[2][2][4];
    const __half* qbase = g_Q + (long long)w * 16384 + h * 32;
#pragma unroll
    for (int mt = 0; mt < 2; ++mt) {
        const int R = (mh * 2 + mt) * 16 + g;
#pragma unroll
        for (int kb = 0; kb < 2; ++kb) {
            const int c = kb * 16 + t * 2;
            qf[mt][kb][0] = *reinterpret_cast<const uint32_t*>(qbase + R * 256 + c);
            qf[mt][kb][1] = *reinterpret_cast<const uint32_t*>(qbase + (R + 8) * 256 + c);
            qf[mt][kb][2] = *reinterpret_cast<const uint32_t*>(qbase + R * 256 + c + 8);
            qf[mt][kb][3] = *reinterpret_cast<const uint32_t*>(qbase + (R + 8) * 256 + c + 8);
        }
    }

    float S[2][8][4];
#pragma unroll
    for (int mt = 0; mt < 2; ++mt)
#pragma unroll
        for (int nb = 0; nb < 8; ++nb)
#pragma unroll
            for (int q = 0; q < 4; ++q) S[mt][nb][q] = 0.f;

#pragma unroll
    for (int nb = 0; nb < 8; ++nb) {
        uint32_t bf[2][2];
#pragma unroll
        for (int kb = 0; kb < 2; ++kb) {
            const __half* p = Kh + (8 * nb + g) * 40 + kb * 16 + t * 2;
            bf[kb][0] = *(const uint32_t*)p;
            bf[kb][1] = *(const uint32_t*)(p + 8);
        }
#pragma unroll
        for (int mt = 0; mt < 2; ++mt)
#pragma unroll
            for (int kb = 0; kb < 2; ++kb)
                mma16816f16(S[mt][nb], qf[mt][kb], bf[kb]);
    }

    const float* bb = g_bias + h * 4096;
#pragma unroll
    for (int mt = 0; mt < 2; ++mt) {
        const int R = (mh * 2 + mt) * 16 + g;
#pragma unroll
        for (int nb = 0; nb < 8; ++nb) {
            const int c = nb * 8 + t * 2;
            float2 b0 = *reinterpret_cast<const float2*>(bb + R * 64 + c);
            float2 b1 = *reinterpret_cast<const float2*>(bb + (R + 8) * 64 + c);
            S[mt][nb][0] += b0.x; S[mt][nb][1] += b0.y;
            S[mt][nb][2] += b1.x; S[mt][nb][3] += b1.y;
        }
    }

    float inv[2][2];
#pragma unroll
    for (int mt = 0; mt < 2; ++mt) {
        float m0 = -1e30f, m1 = -1e30f;
#pragma unroll
        for (int nb = 0; nb < 8; ++nb) {
            m0 = fmaxf(m0, fmaxf(S[mt][nb][0], S[mt][nb][1]));
            m1 = fmaxf(m1, fmaxf(S[mt][nb][2], S[mt][nb][3]));
        }
        m0 = fmaxf(m0, __shfl_xor_sync(0xFFFFFFFF, m0, 1));
        m0 = fmaxf(m0, __shfl_xor_sync(0xFFFFFFFF, m0, 2));
        m1 = fmaxf(m1, __shfl_xor_sync(0xFFFFFFFF, m1, 1));
        m1 = fmaxf(m1, __shfl_xor_sync(0xFFFFFFFF, m1, 2));
        float s0 = 0.f, s1 = 0.f;
#pragma unroll
        for (int nb = 0; nb < 8; ++nb) {
            S[mt][nb][0] = __expf(S[mt][nb][0] - m0);
            S[mt][nb][1] = __expf(S[mt][nb][1] - m0);
            S[mt][nb][2] = __expf(S[mt][nb][2] - m1);
            S[mt][nb][3] = __expf(S[mt][nb][3] - m1);
            s0 += S[mt][nb][0] + S[mt][nb][1];
            s1 += S[mt][nb][2] + S[mt][nb][3];
        }
        s0 += __shfl_xor_sync(0xFFFFFFFF, s0, 1);
        s0 += __shfl_xor_sync(0xFFFFFFFF, s0, 2);
        s1 += __shfl_xor_sync(0xFFFFFFFF, s1, 1);
        s1 += __shfl_xor_sync(0xFFFFFFFF, s1, 2);
        inv[mt][0] = 1.f / s0;
        inv[mt][1] = 1.f / s1;
    }

    uint32_t pf[2][4][4];
#pragma unroll
    for (int mt = 0; mt < 2; ++mt)
#pragma unroll
        for (int kb = 0; kb < 4; ++kb) {
            pf[mt][kb][0] = h2pack(S[mt][2 * kb][0],     S[mt][2 * kb][1]);
            pf[mt][kb][1] = h2pack(S[mt][2 * kb][2],     S[mt][2 * kb][3]);
            pf[mt][kb][2] = h2pack(S[mt][2 * kb + 1][0], S[mt][2 * kb + 1][1]);
            pf[mt][kb][3] = h2pack(S[mt][2 * kb + 1][2], S[mt][2 * kb + 1][3]);
        }

    float O[2][4][4];
#pragma unroll
    for (int mt = 0; mt < 2; ++mt)
#pragma unroll
        for (int nb = 0; nb < 4; ++nb)
#pragma unroll
            for (int q = 0; q < 4; ++q) O[mt][nb][q] = 0.f;

#pragma unroll
    for (int nb = 0; nb < 4; ++nb) {
        uint32_t vf[4][2];
#pragma unroll
        for (int kb = 0; kb < 4; ++kb) {
            const __half* p = Vh + (8 * nb + g) * 72 + kb * 16 + t * 2;
            vf[kb][0] = *(const uint32_t*)p;
            vf[kb][1] = *(const uint32_t*)(p + 8);
        }
#pragma unroll
        for (int mt = 0; mt < 2; ++mt)
#pragma unroll
            for (int kb = 0; kb < 4; ++kb)
                mma16816f16(O[mt][nb], pf[mt][kb], vf[kb]);
    }

    __half* ob = g_O + (long long)w * 16384 + h * 32;
#pragma unroll
    for (int mt = 0; mt < 2; ++mt) {
        const int R = (mh * 2 + mt) * 16 + g;
#pragma unroll
        for (int nb = 0; nb < 4; ++nb) {
            const int c = nb * 8 + t * 2;
            *reinterpret_cast<uint32_t*>(ob + R * 256 + c) =
                h2pack(O[mt][nb][0] * inv[mt][0], O[mt][nb][1] * inv[mt][0]);
            *reinterpret_cast<uint32_t*>(ob + (R + 8) * 256 + c) =
                h2pack(O[mt][nb][2] * inv[mt][1], O[mt][nb][3] * inv[mt][1]);
        }
    }
}

// ---------------------------------------------------------------------------
extern "C" void kernel_launch(void* const* d_in, const int* in_sizes, int n_in,
                              void* d_out, int out_size) {
    const float* xq  = (const float*)d_in[0];
    const float* xs  = (const float*)d_in[1];
    const float* Wq  = (const float*)d_in[2];
    const float* bq  = (const float*)d_in[3];
    const float* Wkv = (const float*)d_in[4];
    const float* bkv = (const float*)d_in[5];
    const float* bt  = (const float*)d_in[6];
    const float* Wp  = (const float*)d_in[7];
    const float* bp  = (const float*)d_in[8];
    float* out = (float*)d_out;

    const int M = in_sizes[0] / 256;            // 262144
    const int B = M / 64;                       // 4096
    const float scale = 0.17677669529663687f;   // 32^-0.5

    cudaFuncSetAttribute(gemm_tc<256, 0, 0>,
                         cudaFuncAttributeMaxDynamicSharedMemorySize, GSM_TOTAL);
    cudaFuncSetAttribute(gemm_tc<512, 1, 0>,
                         cudaFuncAttributeMaxDynamicSharedMemorySize, GSM_TOTAL);
    cudaFuncSetAttribute(gemm_tc<256, 2, 1>,
                         cudaFuncAttributeMaxDynamicSharedMemorySize, GSM_TOTAL);
    cudaFuncSetAttribute(attn_mma,
                         cudaFuncAttributeMaxDynamicSharedMemorySize, ASM_TOTAL);

    // prep: bias + all three W transposes, upfront
    bias_kernel<<<128, 256>>>(bt);
    convw_all<<<1024, 256>>>(Wq, Wkv, Wp);

    gemm_tc<256, 0, 0><<<dim3(2, M / 128), 256, GSM_TOTAL>>>(xq, bq, nullptr, scale, 0);
    gemm_tc<512, 1, 0><<<dim3(4, M / 128), 256, GSM_TOTAL>>>(xs, bkv, nullptr, 1.f, 256);
    attn_mma<<<dim3(B, 2), 256, ASM_TOTAL>>>();
    gemm_tc<256, 2, 1><<<dim3(2, M / 128), 256, GSM_TOTAL>>>(nullptr, bp, out, 1.f, 768);
}